// round 1
// baseline (speedup 1.0000x reference)
#include <cuda_runtime.h>
#include <cuda_bf16.h>
#include <math.h>

#define B_ 4
#define S_ 4096
#define D_ 256

// ---------------- scratch (no allocs allowed) ----------------
__device__ float g_qp[B_ * S_ * D_];
__device__ float g_kp[B_ * S_ * D_];
__device__ float g_vp[B_ * S_ * D_];
__device__ float g_ctx[B_ * S_ * D_];
__device__ float g_attn[(size_t)B_ * S_ * S_];  // fallback if attn not in d_out

// ---------------- tiled GEMM: 64x64x16 tile, 4x4 per thread ----------------
// C[b] = alpha * A[b] @ op(B[b]) (+ bias[n]) (+ mask[m*N+n] * -1e9)
// transB=0: B is [K,N] row-major; transB=1: B is [N,K] row-major (A@B^T)
#define BM 64
#define BN 64
#define BK 16
#define TM 4
#define TN 4

__global__ __launch_bounds__(256)
void gemm64_kernel(const float* __restrict__ A, const float* __restrict__ Bm,
                   const float* __restrict__ bias, const float* __restrict__ mask,
                   float* __restrict__ C,
                   int M, int N, int K, float alpha, int transB,
                   size_t strideA, size_t strideB, size_t strideC)
{
    __shared__ float As[BK][BM];
    __shared__ float Bs[BK][BN];

    const int z = blockIdx.z;
    A  += (size_t)z * strideA;
    Bm += (size_t)z * strideB;
    C  += (size_t)z * strideC;

    const int tx = threadIdx.x;   // 0..15
    const int ty = threadIdx.y;   // 0..15
    const int t  = ty * 16 + tx;  // 0..255

    const int m0 = blockIdx.y * BM;
    const int n0 = blockIdx.x * BN;

    float acc[TM][TN];
#pragma unroll
    for (int i = 0; i < TM; i++)
#pragma unroll
        for (int j = 0; j < TN; j++) acc[i][j] = 0.f;

    // A load mapping: 64 rows x 16 cols, one float4 per thread
    const int ar  = t >> 2;        // 0..63
    const int ac4 = (t & 3) * 4;   // 0,4,8,12
    // B load mapping (NN): 16 rows x 64 cols
    const int br  = t >> 4;        // 0..15
    const int bc4 = (t & 15) * 4;  // 0..60

    for (int k0 = 0; k0 < K; k0 += BK) {
        {
            float4 va = *(const float4*)(A + (size_t)(m0 + ar) * K + k0 + ac4);
            As[ac4 + 0][ar] = va.x; As[ac4 + 1][ar] = va.y;
            As[ac4 + 2][ar] = va.z; As[ac4 + 3][ar] = va.w;
        }
        if (!transB) {
            float4 vb = *(const float4*)(Bm + (size_t)(k0 + br) * N + n0 + bc4);
            *(float4*)(&Bs[br][bc4]) = vb;
        } else {
            // B is [N,K]; load rows n0+ar, cols k0+ac4
            float4 vb = *(const float4*)(Bm + (size_t)(n0 + ar) * K + k0 + ac4);
            Bs[ac4 + 0][ar] = vb.x; Bs[ac4 + 1][ar] = vb.y;
            Bs[ac4 + 2][ar] = vb.z; Bs[ac4 + 3][ar] = vb.w;
        }
        __syncthreads();

#pragma unroll
        for (int k = 0; k < BK; k++) {
            float a[TM], b[TN];
#pragma unroll
            for (int i = 0; i < TM; i++) a[i] = As[k][ty * TM + i];
#pragma unroll
            for (int j = 0; j < TN; j++) b[j] = Bs[k][tx * TN + j];
#pragma unroll
            for (int i = 0; i < TM; i++)
#pragma unroll
                for (int j = 0; j < TN; j++) acc[i][j] = fmaf(a[i], b[j], acc[i][j]);
        }
        __syncthreads();
    }

#pragma unroll
    for (int i = 0; i < TM; i++) {
        const int m = m0 + ty * TM + i;
#pragma unroll
        for (int j = 0; j < TN; j++) {
            const int n = n0 + tx * TN + j;
            float vv = acc[i][j] * alpha;
            if (bias) vv += bias[n];
            if (mask) vv += mask[(size_t)m * N + n] * (-1e9f);
            C[(size_t)m * N + n] = vv;
        }
    }
}

// ---------------- row softmax over S=4096, one block per row ----------------
__global__ __launch_bounds__(256)
void softmax_kernel(float* __restrict__ attn)
{
    __shared__ float buf[S_];
    __shared__ float red[8];
    __shared__ float s_max, s_sum;

    float* row = attn + (size_t)blockIdx.x * S_;
    const int t = threadIdx.x;

    float mx = -1e30f;
    for (int i = t * 4; i < S_; i += 1024) {
        float4 v = *(const float4*)(row + i);
        *(float4*)(buf + i) = v;
        mx = fmaxf(mx, fmaxf(fmaxf(v.x, v.y), fmaxf(v.z, v.w)));
    }
#pragma unroll
    for (int o = 16; o; o >>= 1) mx = fmaxf(mx, __shfl_xor_sync(0xffffffffu, mx, o));
    if ((t & 31) == 0) red[t >> 5] = mx;
    __syncthreads();
    if (t == 0) {
        float m = red[0];
#pragma unroll
        for (int i = 1; i < 8; i++) m = fmaxf(m, red[i]);
        s_max = m;
    }
    __syncthreads();
    const float m = s_max;

    float sum = 0.f;
    for (int i = t * 4; i < S_; i += 1024) {
        float4 v = *(const float4*)(buf + i);
        v.x = __expf(v.x - m); v.y = __expf(v.y - m);
        v.z = __expf(v.z - m); v.w = __expf(v.w - m);
        *(float4*)(buf + i) = v;
        sum += v.x + v.y + v.z + v.w;
    }
#pragma unroll
    for (int o = 16; o; o >>= 1) sum += __shfl_xor_sync(0xffffffffu, sum, o);
    if ((t & 31) == 0) red[t >> 5] = sum;
    __syncthreads();
    if (t == 0) {
        float s = red[0];
#pragma unroll
        for (int i = 1; i < 8; i++) s += red[i];
        s_sum = s;
    }
    __syncthreads();
    const float inv = 1.f / s_sum;

    for (int i = t * 4; i < S_; i += 1024) {
        float4 v = *(const float4*)(buf + i);
        v.x *= inv; v.y *= inv; v.z *= inv; v.w *= inv;
        *(float4*)(row + i) = v;
    }
}

// ---------------- launch ----------------
extern "C" void kernel_launch(void* const* d_in, const int* in_sizes, int n_in,
                              void* d_out, int out_size)
{
    const float* q    = (const float*)d_in[0];
    const float* k    = (const float*)d_in[1];
    const float* v    = (const float*)d_in[2];
    const float* mask = (const float*)d_in[3];
    const float* Wq   = (const float*)d_in[4];
    const float* bq   = (const float*)d_in[5];
    const float* Wk   = (const float*)d_in[6];
    const float* bk   = (const float*)d_in[7];
    const float* Wv   = (const float*)d_in[8];
    const float* bv   = (const float*)d_in[9];
    const float* Wo   = (const float*)d_in[10];
    const float* bo   = (const float*)d_in[11];

    float *qp, *kp, *vp, *ctx, *attn_scr;
    cudaGetSymbolAddress((void**)&qp,  g_qp);
    cudaGetSymbolAddress((void**)&kp,  g_kp);
    cudaGetSymbolAddress((void**)&vp,  g_vp);
    cudaGetSymbolAddress((void**)&ctx, g_ctx);
    cudaGetSymbolAddress((void**)&attn_scr, g_attn);

    const size_t zN = (size_t)B_ * S_ * D_;        // 4,194,304
    const size_t aN = (size_t)B_ * S_ * S_;        // 67,108,864

    float* out = (float*)d_out;
    float* z_out;
    float* attn_out;
    if ((size_t)out_size >= zN + aN) {             // (z, attn) flattened
        z_out = out; attn_out = out + zN;
    } else if ((size_t)out_size == aN) {           // attn only
        attn_out = out; z_out = kp;                // kp dead after logits
    } else {                                       // z only
        z_out = out; attn_out = attn_scr;
    }

    dim3 blk(16, 16);
    const float inv_sqrt_d = 1.0f / 16.0f;         // 1/sqrt(256)

    // projections: [16384,256] @ [256,256] + b
    dim3 gproj(D_ / BN, (B_ * S_) / BM, 1);
    gemm64_kernel<<<gproj, blk>>>(q, Wq, bq, nullptr, qp, B_ * S_, D_, D_, 1.f, 0, 0, 0, 0);
    gemm64_kernel<<<gproj, blk>>>(k, Wk, bk, nullptr, kp, B_ * S_, D_, D_, 1.f, 0, 0, 0, 0);
    gemm64_kernel<<<gproj, blk>>>(v, Wv, bv, nullptr, vp, B_ * S_, D_, D_, 1.f, 0, 0, 0, 0);

    // logits: per-batch qp @ kp^T / 16 + mask * -1e9
    dim3 glog(S_ / BN, S_ / BM, B_);
    gemm64_kernel<<<glog, blk>>>(qp, kp, nullptr, mask, attn_out,
                                 S_, S_, D_, inv_sqrt_d, 1,
                                 (size_t)S_ * D_, (size_t)S_ * D_, (size_t)S_ * S_);

    // softmax rows
    softmax_kernel<<<B_ * S_, 256>>>(attn_out);

    // ctx: per-batch attn @ vp  ([4096,4096] @ [4096,256])
    dim3 gctx(D_ / BN, S_ / BM, B_);
    gemm64_kernel<<<gctx, blk>>>(attn_out, vp, nullptr, nullptr, ctx,
                                 S_, D_, S_, 1.f, 0,
                                 (size_t)S_ * S_, (size_t)S_ * D_, (size_t)S_ * D_);

    // z = ctx @ Wo + bo
    gemm64_kernel<<<gproj, blk>>>(ctx, Wo, bo, nullptr, z_out, B_ * S_, D_, D_, 1.f, 0, 0, 0, 0);
}

// round 2
// speedup vs baseline: 1.0019x; 1.0019x over previous
#include <cuda_runtime.h>
#include <cuda_bf16.h>
#include <math.h>

#define B_ 4
#define S_ 4096
#define D_ 256

// ---------------- scratch (no allocs allowed) ----------------
__device__ float g_qp[B_ * S_ * D_];
__device__ float g_kp[B_ * S_ * D_];
__device__ float g_vp[B_ * S_ * D_];
__device__ float g_ctx[B_ * S_ * D_];
__device__ float g_attn[(size_t)B_ * S_ * S_];  // fallback if attn not in d_out

// ---------------- tiled GEMM: 64x64x16 tile, 4x4 per thread ----------------
// C[b] = alpha * A[b] @ op(B[b]) (+ bias[n]) (+ mask[m*N+n] * -1e9)
// transB=0: B is [K,N] row-major; transB=1: B is [N,K] row-major (A@B^T)
#define BM 64
#define BN 64
#define BK 16
#define TM 4
#define TN 4

__global__ __launch_bounds__(256)
void gemm64_kernel(const float* __restrict__ A, const float* __restrict__ Bm,
                   const float* __restrict__ bias, const float* __restrict__ mask,
                   float* __restrict__ C,
                   int M, int N, int K, float alpha, int transB,
                   size_t strideA, size_t strideB, size_t strideC)
{
    __shared__ float As[BK][BM];
    __shared__ float Bs[BK][BN];

    const int z = blockIdx.z;
    A  += (size_t)z * strideA;
    Bm += (size_t)z * strideB;
    C  += (size_t)z * strideC;

    const int tx = threadIdx.x;   // 0..15
    const int ty = threadIdx.y;   // 0..15
    const int t  = ty * 16 + tx;  // 0..255

    const int m0 = blockIdx.y * BM;
    const int n0 = blockIdx.x * BN;

    float acc[TM][TN];
#pragma unroll
    for (int i = 0; i < TM; i++)
#pragma unroll
        for (int j = 0; j < TN; j++) acc[i][j] = 0.f;

    // A load mapping: 64 rows x 16 cols, one float4 per thread
    const int ar  = t >> 2;        // 0..63
    const int ac4 = (t & 3) * 4;   // 0,4,8,12
    // B load mapping (NN): 16 rows x 64 cols
    const int br  = t >> 4;        // 0..15
    const int bc4 = (t & 15) * 4;  // 0..60

    for (int k0 = 0; k0 < K; k0 += BK) {
        {
            float4 va = *(const float4*)(A + (size_t)(m0 + ar) * K + k0 + ac4);
            As[ac4 + 0][ar] = va.x; As[ac4 + 1][ar] = va.y;
            As[ac4 + 2][ar] = va.z; As[ac4 + 3][ar] = va.w;
        }
        if (!transB) {
            float4 vb = *(const float4*)(Bm + (size_t)(k0 + br) * N + n0 + bc4);
            *(float4*)(&Bs[br][bc4]) = vb;
        } else {
            // B is [N,K]; load rows n0+ar, cols k0+ac4
            float4 vb = *(const float4*)(Bm + (size_t)(n0 + ar) * K + k0 + ac4);
            Bs[ac4 + 0][ar] = vb.x; Bs[ac4 + 1][ar] = vb.y;
            Bs[ac4 + 2][ar] = vb.z; Bs[ac4 + 3][ar] = vb.w;
        }
        __syncthreads();

#pragma unroll
        for (int k = 0; k < BK; k++) {
            float a[TM], b[TN];
#pragma unroll
            for (int i = 0; i < TM; i++) a[i] = As[k][ty * TM + i];
#pragma unroll
            for (int j = 0; j < TN; j++) b[j] = Bs[k][tx * TN + j];
#pragma unroll
            for (int i = 0; i < TM; i++)
#pragma unroll
                for (int j = 0; j < TN; j++) acc[i][j] = fmaf(a[i], b[j], acc[i][j]);
        }
        __syncthreads();
    }

#pragma unroll
    for (int i = 0; i < TM; i++) {
        const int m = m0 + ty * TM + i;
#pragma unroll
        for (int j = 0; j < TN; j++) {
            const int n = n0 + tx * TN + j;
            float vv = acc[i][j] * alpha;
            if (bias) vv += bias[n];
            if (mask) vv += mask[(size_t)m * N + n] * (-1e9f);
            C[(size_t)m * N + n] = vv;
        }
    }
}

// ---------------- row softmax over S=4096, one block per row ----------------
__global__ __launch_bounds__(256)
void softmax_kernel(float* __restrict__ attn)
{
    __shared__ float buf[S_];
    __shared__ float red[8];
    __shared__ float s_max, s_sum;

    float* row = attn + (size_t)blockIdx.x * S_;
    const int t = threadIdx.x;

    float mx = -1e30f;
    for (int i = t * 4; i < S_; i += 1024) {
        float4 v = *(const float4*)(row + i);
        *(float4*)(buf + i) = v;
        mx = fmaxf(mx, fmaxf(fmaxf(v.x, v.y), fmaxf(v.z, v.w)));
    }
#pragma unroll
    for (int o = 16; o; o >>= 1) mx = fmaxf(mx, __shfl_xor_sync(0xffffffffu, mx, o));
    if ((t & 31) == 0) red[t >> 5] = mx;
    __syncthreads();
    if (t == 0) {
        float m = red[0];
#pragma unroll
        for (int i = 1; i < 8; i++) m = fmaxf(m, red[i]);
        s_max = m;
    }
    __syncthreads();
    const float m = s_max;

    float sum = 0.f;
    for (int i = t * 4; i < S_; i += 1024) {
        float4 v = *(const float4*)(buf + i);
        v.x = __expf(v.x - m); v.y = __expf(v.y - m);
        v.z = __expf(v.z - m); v.w = __expf(v.w - m);
        *(float4*)(buf + i) = v;
        sum += v.x + v.y + v.z + v.w;
    }
#pragma unroll
    for (int o = 16; o; o >>= 1) sum += __shfl_xor_sync(0xffffffffu, sum, o);
    if ((t & 31) == 0) red[t >> 5] = sum;
    __syncthreads();
    if (t == 0) {
        float s = red[0];
#pragma unroll
        for (int i = 1; i < 8; i++) s += red[i];
        s_sum = s;
    }
    __syncthreads();
    const float inv = 1.f / s_sum;

    for (int i = t * 4; i < S_; i += 1024) {
        float4 v = *(const float4*)(buf + i);
        v.x *= inv; v.y *= inv; v.z *= inv; v.w *= inv;
        *(float4*)(row + i) = v;
    }
}

// ---------------- launch ----------------
extern "C" void kernel_launch(void* const* d_in, const int* in_sizes, int n_in,
                              void* d_out, int out_size)
{
    const float* q    = (const float*)d_in[0];
    const float* k    = (const float*)d_in[1];
    const float* v    = (const float*)d_in[2];
    const float* mask = (const float*)d_in[3];
    const float* Wq   = (const float*)d_in[4];
    const float* bq   = (const float*)d_in[5];
    const float* Wk   = (const float*)d_in[6];
    const float* bk   = (const float*)d_in[7];
    const float* Wv   = (const float*)d_in[8];
    const float* bv   = (const float*)d_in[9];
    const float* Wo   = (const float*)d_in[10];
    const float* bo   = (const float*)d_in[11];

    float *qp, *kp, *vp, *ctx, *attn_scr;
    cudaGetSymbolAddress((void**)&qp,  g_qp);
    cudaGetSymbolAddress((void**)&kp,  g_kp);
    cudaGetSymbolAddress((void**)&vp,  g_vp);
    cudaGetSymbolAddress((void**)&ctx, g_ctx);
    cudaGetSymbolAddress((void**)&attn_scr, g_attn);

    const size_t zN = (size_t)B_ * S_ * D_;        // 4,194,304
    const size_t aN = (size_t)B_ * S_ * S_;        // 67,108,864

    float* out = (float*)d_out;
    float* z_out;
    float* attn_out;
    if ((size_t)out_size >= zN + aN) {             // (z, attn) flattened
        z_out = out; attn_out = out + zN;
    } else if ((size_t)out_size == aN) {           // attn only
        attn_out = out; z_out = kp;                // kp dead after logits
    } else {                                       // z only
        z_out = out; attn_out = attn_scr;
    }

    dim3 blk(16, 16);
    const float inv_sqrt_d = 1.0f / 16.0f;         // 1/sqrt(256)

    // projections: [16384,256] @ [256,256] + b
    dim3 gproj(D_ / BN, (B_ * S_) / BM, 1);
    gemm64_kernel<<<gproj, blk>>>(q, Wq, bq, nullptr, qp, B_ * S_, D_, D_, 1.f, 0, 0, 0, 0);
    gemm64_kernel<<<gproj, blk>>>(k, Wk, bk, nullptr, kp, B_ * S_, D_, D_, 1.f, 0, 0, 0, 0);
    gemm64_kernel<<<gproj, blk>>>(v, Wv, bv, nullptr, vp, B_ * S_, D_, D_, 1.f, 0, 0, 0, 0);

    // logits: per-batch qp @ kp^T / 16 + mask * -1e9
    dim3 glog(S_ / BN, S_ / BM, B_);
    gemm64_kernel<<<glog, blk>>>(qp, kp, nullptr, mask, attn_out,
                                 S_, S_, D_, inv_sqrt_d, 1,
                                 (size_t)S_ * D_, (size_t)S_ * D_, (size_t)S_ * S_);

    // softmax rows
    softmax_kernel<<<B_ * S_, 256>>>(attn_out);

    // ctx: per-batch attn @ vp  ([4096,4096] @ [4096,256])
    dim3 gctx(D_ / BN, S_ / BM, B_);
    gemm64_kernel<<<gctx, blk>>>(attn_out, vp, nullptr, nullptr, ctx,
                                 S_, D_, S_, 1.f, 0,
                                 (size_t)S_ * S_, (size_t)S_ * D_, (size_t)S_ * D_);

    // z = ctx @ Wo + bo
    gemm64_kernel<<<gproj, blk>>>(ctx, Wo, bo, nullptr, z_out, B_ * S_, D_, D_, 1.f, 0, 0, 0, 0);
}

// round 4
// speedup vs baseline: 2.2484x; 2.2442x over previous
#include <cuda_runtime.h>
#include <cuda_bf16.h>
#include <cstdint>
#include <math.h>

#define B_ 4
#define S_ 4096
#define D_ 256
#define BS_ (B_ * S_)

#define TILE_M 128
#define TILE_N 128
#define TILE_K 64

// ---------------- scratch (__device__ globals; no allocs) ----------------
__device__ __nv_bfloat16 g_q_hi[BS_ * D_], g_q_lo[BS_ * D_];
__device__ __nv_bfloat16 g_k_hi[BS_ * D_], g_k_lo[BS_ * D_];
__device__ __nv_bfloat16 g_v_hi[BS_ * D_], g_v_lo[BS_ * D_];
__device__ __nv_bfloat16 g_qp_hi[BS_ * D_], g_qp_lo[BS_ * D_];
__device__ __nv_bfloat16 g_kp_hi[BS_ * D_], g_kp_lo[BS_ * D_];
__device__ float         g_vp[BS_ * D_];
__device__ __nv_bfloat16 g_vpT_hi[BS_ * D_], g_vpT_lo[BS_ * D_];
__device__ __nv_bfloat16 g_ctx_hi[BS_ * D_], g_ctx_lo[BS_ * D_];
__device__ __nv_bfloat16 g_WT_hi[4][D_ * D_], g_WT_lo[4][D_ * D_];
__device__ __nv_bfloat16 g_attn_hi[(size_t)B_ * S_ * S_];
__device__ __nv_bfloat16 g_attn_lo[(size_t)B_ * S_ * S_];
__device__ float         g_attn_f[(size_t)B_ * S_ * S_];   // fallback
__device__ float         g_z[BS_ * D_];                    // fallback

// ---------------- helpers ----------------
__device__ __forceinline__ uint32_t smem_u32(const void* p) {
    uint32_t a;
    asm("{ .reg .u64 t; cvta.to.shared.u64 t, %1; cvt.u32.u64 %0, t; }" : "=r"(a) : "l"(p));
    return a;
}
#define SWZ128(o) ((o) ^ (((o) >> 3) & 0x70))

__device__ __forceinline__ void cpa16(uint32_t s, const void* g) {
    asm volatile("cp.async.cg.shared.global [%0], [%1], 16;" :: "r"(s), "l"(g));
}
#define CP_COMMIT() asm volatile("cp.async.commit_group;")
#define CP_WAIT1()  asm volatile("cp.async.wait_group 1;" ::: "memory")
#define CP_WAIT0()  asm volatile("cp.async.wait_group 0;" ::: "memory")

__device__ __forceinline__ void ldm_x4(uint32_t* r, uint32_t addr) {
    asm volatile("ldmatrix.sync.aligned.m8n8.x4.shared.b16 {%0,%1,%2,%3}, [%4];"
                 : "=r"(r[0]), "=r"(r[1]), "=r"(r[2]), "=r"(r[3]) : "r"(addr));
}
__device__ __forceinline__ void mma16816(float* c, const uint32_t* a, const uint32_t* b) {
    asm volatile("mma.sync.aligned.m16n8k16.row.col.f32.bf16.bf16.f32 "
                 "{%0,%1,%2,%3}, {%4,%5,%6,%7}, {%8,%9}, {%0,%1,%2,%3};"
                 : "+f"(c[0]), "+f"(c[1]), "+f"(c[2]), "+f"(c[3])
                 : "r"(a[0]), "r"(a[1]), "r"(a[2]), "r"(a[3]), "r"(b[0]), "r"(b[1]));
}

__device__ __forceinline__ uint32_t pack_bf2(float a, float b) {
    uint32_t r;
    asm("cvt.rn.bf16x2.f32 %0, %1, %2;" : "=r"(r) : "f"(b), "f"(a));
    return r;
}
__device__ __forceinline__ void residual2(uint32_t h, float a, float b, float& ra, float& rb) {
    ra = a - __uint_as_float(h << 16);
    rb = b - __uint_as_float(h & 0xffff0000u);
}

// ----------------------------------------------------------------------------
// mma.sync bf16x3 GEMM:  C[z] = alpha * A[z] @ B[z]^T (+bias) (+mask*-1e9)
// A: [M,K] hi/lo bf16 row-major; B: [N,K] hi/lo bf16 row-major
// CTA tile 128x128, K-chunk 64, double-buffered cp.async, 8 warps of 64x32.
// ----------------------------------------------------------------------------
#define OFF_AH 0
#define OFF_AL 16384
#define OFF_BH 32768
#define OFF_BL 49152
#define STAGE_B 65536
#define SMEM_GEMM (2 * STAGE_B)

__device__ __forceinline__ void tile_cp(uint32_t sbase, const __nv_bfloat16* g,
                                        size_t ldK, int tid) {
    // 128 rows x 64 bf16 (128B) per tile, SW128 swizzled; 1024 16B-chunks
#pragma unroll
    for (int i = 0; i < 4; i++) {
        int u = tid + (i << 8);
        int r = u >> 3, c = u & 7;
        uint32_t off = (uint32_t)(r * 128 + c * 16);
        cpa16(sbase + SWZ128(off), (const char*)(g + (size_t)r * ldK) + (c << 4));
    }
}

__global__ __launch_bounds__(256, 1)
void gemm_mma(const __nv_bfloat16* __restrict__ Ahi, const __nv_bfloat16* __restrict__ Alo,
              const __nv_bfloat16* __restrict__ Bhi, const __nv_bfloat16* __restrict__ Blo,
              int N, int K,
              size_t sA, size_t sB, size_t sC,
              float alpha, const float* __restrict__ bias,
              const float* __restrict__ mask, int maskLd,
              float* __restrict__ Cf,
              __nv_bfloat16* __restrict__ Chi, __nv_bfloat16* __restrict__ Clo)
{
    extern __shared__ char dsm[];
    const uint32_t sb = smem_u32(dsm);
    const int tid = threadIdx.x;
    const int wid = tid >> 5;
    const int lane = tid & 31;

    const int z = blockIdx.z;
    Ahi += (size_t)z * sA; Alo += (size_t)z * sA;
    Bhi += (size_t)z * sB; Blo += (size_t)z * sB;
    if (Cf)  Cf  += (size_t)z * sC;
    if (Chi) { Chi += (size_t)z * sC; Clo += (size_t)z * sC; }

    const int m0 = blockIdx.y * TILE_M;
    const int n0 = blockIdx.x * TILE_N;

    const int mrow0 = (wid & 1) * 64;    // warp M offset (2 rows of warps)
    const int ncol0 = (wid >> 1) * 32;   // warp N offset (4 cols of warps)

    const __nv_bfloat16* aH = Ahi + (size_t)m0 * K;
    const __nv_bfloat16* aL = Alo + (size_t)m0 * K;
    const __nv_bfloat16* bH = Bhi + (size_t)n0 * K;
    const __nv_bfloat16* bL = Blo + (size_t)n0 * K;

    float acc[4][4][4];
#pragma unroll
    for (int i = 0; i < 4; i++)
#pragma unroll
        for (int j = 0; j < 4; j++)
#pragma unroll
            for (int l = 0; l < 4; l++) acc[i][j][l] = 0.f;

    const int NC = K / TILE_K;

    // prefetch chunk 0 into stage 0
    {
        const uint32_t st = sb;
        tile_cp(st + OFF_AH, aH, K, tid);
        tile_cp(st + OFF_AL, aL, K, tid);
        tile_cp(st + OFF_BH, bH, K, tid);
        tile_cp(st + OFF_BL, bL, K, tid);
        CP_COMMIT();
    }

    const uint32_t lane15 = (uint32_t)(lane & 15);
    const uint32_t khalf = (uint32_t)((lane >> 4) << 4);  // 0 or 16 bytes

    for (int c = 0; c < NC; c++) {
        if (c + 1 < NC) {
            const uint32_t st = sb + ((c + 1) & 1) * STAGE_B;
            const size_t ko = (size_t)(c + 1) * TILE_K;
            tile_cp(st + OFF_AH, aH + ko, K, tid);
            tile_cp(st + OFF_AL, aL + ko, K, tid);
            tile_cp(st + OFF_BH, bH + ko, K, tid);
            tile_cp(st + OFF_BL, bL + ko, K, tid);
            CP_COMMIT();
            CP_WAIT1();
        } else {
            CP_WAIT0();
        }
        __syncthreads();

        const uint32_t st = sb + (c & 1) * STAGE_B;
        const uint32_t sAh = st + OFF_AH, sAl = st + OFF_AL;
        const uint32_t sBh = st + OFF_BH, sBl = st + OFF_BL;

#pragma unroll
        for (int ks = 0; ks < 4; ks++) {
            const uint32_t kb = (uint32_t)(ks * 32) + khalf;  // byte offset of k16 block
            uint32_t ah[4][4], al[4][4], bh[4][2], bl[4][2];
#pragma unroll
            for (int mt = 0; mt < 4; mt++) {
                const uint32_t ro = (uint32_t)(mrow0 + mt * 16) + lane15;
                ldm_x4(ah[mt], sAh + SWZ128(ro * 128 + kb));
                ldm_x4(al[mt], sAl + SWZ128(ro * 128 + kb));
            }
#pragma unroll
            for (int g = 0; g < 2; g++) {
                const uint32_t ro = (uint32_t)(ncol0 + g * 16) + lane15;
                uint32_t t4[4];
                ldm_x4(t4, sBh + SWZ128(ro * 128 + kb));
                bh[g * 2][0] = t4[0]; bh[g * 2][1] = t4[2];
                bh[g * 2 + 1][0] = t4[1]; bh[g * 2 + 1][1] = t4[3];
                ldm_x4(t4, sBl + SWZ128(ro * 128 + kb));
                bl[g * 2][0] = t4[0]; bl[g * 2][1] = t4[2];
                bl[g * 2 + 1][0] = t4[1]; bl[g * 2 + 1][1] = t4[3];
            }
#pragma unroll
            for (int mt = 0; mt < 4; mt++)
#pragma unroll
                for (int nt = 0; nt < 4; nt++) {
                    mma16816(acc[mt][nt], ah[mt], bh[nt]);
                    mma16816(acc[mt][nt], ah[mt], bl[nt]);
                    mma16816(acc[mt][nt], al[mt], bh[nt]);
                }
        }
        __syncthreads();
    }

    // ---- epilogue: regs -> smem stage -> coalesced gmem ----
    float* stg = (float*)dsm;
    const int ELD = 132;
    const int rr = lane >> 2;
    const int cc = (lane & 3) * 2;
#pragma unroll
    for (int mt = 0; mt < 4; mt++)
#pragma unroll
        for (int nt = 0; nt < 4; nt++) {
            const int r = mrow0 + mt * 16 + rr;
            const int cn = ncol0 + nt * 8 + cc;
            stg[r * ELD + cn]           = acc[mt][nt][0];
            stg[r * ELD + cn + 1]       = acc[mt][nt][1];
            stg[(r + 8) * ELD + cn]     = acc[mt][nt][2];
            stg[(r + 8) * ELD + cn + 1] = acc[mt][nt][3];
        }
    __syncthreads();

#pragma unroll 1
    for (int it = 0; it < 16; it++) {
        const int u = tid + (it << 8);       // 0..4095
        const int r = u >> 5;                // row 0..127
        const int f = (u & 31) << 2;         // col 0..124 step 4
        const float* s = stg + r * ELD + f;
        float v0 = s[0] * alpha, v1 = s[1] * alpha, v2 = s[2] * alpha, v3 = s[3] * alpha;
        const int n = n0 + f;
        const size_t m = (size_t)(m0 + r);
        if (bias) {
            float4 bv = *(const float4*)(bias + n);
            v0 += bv.x; v1 += bv.y; v2 += bv.z; v3 += bv.w;
        }
        if (mask) {
            float4 mv = *(const float4*)(mask + m * (size_t)maskLd + n);
            v0 += mv.x * (-1e9f); v1 += mv.y * (-1e9f);
            v2 += mv.z * (-1e9f); v3 += mv.w * (-1e9f);
        }
        const size_t o = m * (size_t)N + n;
        if (Cf) {
            float4 ov = {v0, v1, v2, v3};
            *(float4*)(Cf + o) = ov;
        }
        if (Chi) {
            uint32_t h0 = pack_bf2(v0, v1), h1 = pack_bf2(v2, v3);
            float r0, r1, r2, r3;
            residual2(h0, v0, v1, r0, r1);
            residual2(h1, v2, v3, r2, r3);
            uint2 hv = {h0, h1};
            uint2 lv = {pack_bf2(r0, r1), pack_bf2(r2, r3)};
            *(uint2*)(Chi + o) = hv;
            *(uint2*)(Clo + o) = lv;
        }
    }
}

// ---------------- fp32 -> (hi, lo) bf16 ----------------
__global__ __launch_bounds__(256)
void convert_hilo(const float* __restrict__ in, __nv_bfloat16* __restrict__ hi,
                  __nv_bfloat16* __restrict__ lo, int n4)
{
    int i = blockIdx.x * blockDim.x + threadIdx.x;
    if (i >= n4) return;
    float4 v = ((const float4*)in)[i];
    uint32_t h0 = pack_bf2(v.x, v.y), h1 = pack_bf2(v.z, v.w);
    float r0, r1, r2, r3;
    residual2(h0, v.x, v.y, r0, r1);
    residual2(h1, v.z, v.w, r2, r3);
    uint2 hv = {h0, h1};
    uint2 lv = {pack_bf2(r0, r1), pack_bf2(r2, r3)};
    ((uint2*)hi)[i] = hv;
    ((uint2*)lo)[i] = lv;
}

// ---------------- transpose + split: [Z,R,C] f32 -> [Z,C,R] hi/lo ----------------
__global__ __launch_bounds__(256)
void transpose_hilo(const float* __restrict__ in, __nv_bfloat16* __restrict__ ohi,
                    __nv_bfloat16* __restrict__ olo, int R, int C)
{
    __shared__ float t[32][33];
    const int z = blockIdx.z;
    in  += (size_t)z * R * C;
    ohi += (size_t)z * R * C;
    olo += (size_t)z * R * C;
    const int r0 = blockIdx.y * 32, c0 = blockIdx.x * 32;
    const int tx = threadIdx.x, ty = threadIdx.y;
#pragma unroll
    for (int j = 0; j < 32; j += 8)
        t[ty + j][tx] = in[(size_t)(r0 + ty + j) * C + c0 + tx];
    __syncthreads();
#pragma unroll
    for (int j = 0; j < 32; j += 8) {
        float v = t[tx][ty + j];
        __nv_bfloat16 h = __float2bfloat16(v);
        __nv_bfloat16 l = __float2bfloat16(v - __bfloat162float(h));
        size_t o = (size_t)(c0 + ty + j) * R + r0 + tx;
        ohi[o] = h; olo[o] = l;
    }
}

// ---------------- softmax rows of [B*S, S]; emits fp32 + hi/lo ----------------
__global__ __launch_bounds__(256)
void softmax_kernel(float* __restrict__ attn, __nv_bfloat16* __restrict__ ahi,
                    __nv_bfloat16* __restrict__ alo)
{
    __shared__ float buf[S_];
    __shared__ float red[8];
    __shared__ float s_max, s_sum;

    const size_t rb = (size_t)blockIdx.x * S_;
    float* row = attn + rb;
    const int t = threadIdx.x;

    float mx = -1e30f;
    for (int i = t * 4; i < S_; i += 1024) {
        float4 v = *(const float4*)(row + i);
        *(float4*)(buf + i) = v;
        mx = fmaxf(mx, fmaxf(fmaxf(v.x, v.y), fmaxf(v.z, v.w)));
    }
#pragma unroll
    for (int o = 16; o; o >>= 1) mx = fmaxf(mx, __shfl_xor_sync(0xffffffffu, mx, o));
    if ((t & 31) == 0) red[t >> 5] = mx;
    __syncthreads();
    if (t == 0) {
        float m = red[0];
#pragma unroll
        for (int i = 1; i < 8; i++) m = fmaxf(m, red[i]);
        s_max = m;
    }
    __syncthreads();
    const float m = s_max;

    float sum = 0.f;
    for (int i = t * 4; i < S_; i += 1024) {
        float4 v = *(const float4*)(buf + i);
        v.x = __expf(v.x - m); v.y = __expf(v.y - m);
        v.z = __expf(v.z - m); v.w = __expf(v.w - m);
        *(float4*)(buf + i) = v;
        sum += v.x + v.y + v.z + v.w;
    }
#pragma unroll
    for (int o = 16; o; o >>= 1) sum += __shfl_xor_sync(0xffffffffu, sum, o);
    if ((t & 31) == 0) red[t >> 5] = sum;
    __syncthreads();
    if (t == 0) {
        float s = red[0];
#pragma unroll
        for (int i = 1; i < 8; i++) s += red[i];
        s_sum = s;
    }
    __syncthreads();
    const float inv = 1.f / s_sum;

    for (int i = t * 4; i < S_; i += 1024) {
        float4 v = *(const float4*)(buf + i);
        v.x *= inv; v.y *= inv; v.z *= inv; v.w *= inv;
        *(float4*)(row + i) = v;
        uint32_t h0 = pack_bf2(v.x, v.y), h1 = pack_bf2(v.z, v.w);
        float r0, r1, r2, r3;
        residual2(h0, v.x, v.y, r0, r1);
        residual2(h1, v.z, v.w, r2, r3);
        uint2 hv = {h0, h1};
        uint2 lv = {pack_bf2(r0, r1), pack_bf2(r2, r3)};
        *(uint2*)(ahi + rb + i) = hv;
        *(uint2*)(alo + rb + i) = lv;
    }
}

// ---------------- launch ----------------
extern "C" void kernel_launch(void* const* d_in, const int* in_sizes, int n_in,
                              void* d_out, int out_size)
{
    const float* q    = (const float*)d_in[0];
    const float* k    = (const float*)d_in[1];
    const float* v    = (const float*)d_in[2];
    const float* mask = (const float*)d_in[3];
    const float* Wq   = (const float*)d_in[4];
    const float* bq   = (const float*)d_in[5];
    const float* Wk   = (const float*)d_in[6];
    const float* bk   = (const float*)d_in[7];
    const float* Wv   = (const float*)d_in[8];
    const float* bv   = (const float*)d_in[9];
    const float* Wo   = (const float*)d_in[10];
    const float* bo   = (const float*)d_in[11];

#define SYM(p, s) cudaGetSymbolAddress((void**)&p, s)
    __nv_bfloat16 *qh, *ql, *kh, *kl, *vh, *vl;
    __nv_bfloat16 *qph, *qpl, *kph, *kpl, *vpTh, *vpTl, *ctxh, *ctxl, *ath, *atl;
    __nv_bfloat16 *WTh, *WTl;
    float *vp, *attn_scr, *z_scr;
    SYM(qh, g_q_hi);  SYM(ql, g_q_lo);
    SYM(kh, g_k_hi);  SYM(kl, g_k_lo);
    SYM(vh, g_v_hi);  SYM(vl, g_v_lo);
    SYM(qph, g_qp_hi); SYM(qpl, g_qp_lo);
    SYM(kph, g_kp_hi); SYM(kpl, g_kp_lo);
    SYM(vp, g_vp);
    SYM(vpTh, g_vpT_hi); SYM(vpTl, g_vpT_lo);
    SYM(ctxh, g_ctx_hi); SYM(ctxl, g_ctx_lo);
    SYM(ath, g_attn_hi); SYM(atl, g_attn_lo);
    SYM(WTh, (g_WT_hi[0][0]));   SYM(WTl, (g_WT_lo[0][0]));
    SYM(attn_scr, g_attn_f); SYM(z_scr, g_z);

    const size_t zN = (size_t)BS_ * D_;
    const size_t aN = (size_t)B_ * S_ * S_;
    float* out = (float*)d_out;
    float *z_out, *attn_out;
    if ((size_t)out_size >= zN + aN) { z_out = out; attn_out = out + zN; }
    else if ((size_t)out_size == aN) { attn_out = out; z_out = z_scr; }
    else                             { z_out = out; attn_out = attn_scr; }

    cudaFuncSetAttribute(gemm_mma, cudaFuncAttributeMaxDynamicSharedMemorySize, SMEM_GEMM);

    // 1) split inputs
    const int n4 = BS_ * D_ / 4;
    convert_hilo<<<(n4 + 255) / 256, 256>>>(q, qh, ql, n4);
    convert_hilo<<<(n4 + 255) / 256, 256>>>(k, kh, kl, n4);
    convert_hilo<<<(n4 + 255) / 256, 256>>>(v, vh, vl, n4);

    // 2) transpose+split weights: W [K,N] -> WT [N,K]
    dim3 tb(32, 8);
    dim3 tgw(D_ / 32, D_ / 32, 1);
    transpose_hilo<<<tgw, tb>>>(Wq, WTh + 0 * D_ * D_, WTl + 0 * D_ * D_, D_, D_);
    transpose_hilo<<<tgw, tb>>>(Wk, WTh + 1 * D_ * D_, WTl + 1 * D_ * D_, D_, D_);
    transpose_hilo<<<tgw, tb>>>(Wv, WTh + 2 * D_ * D_, WTl + 2 * D_ * D_, D_, D_);
    transpose_hilo<<<tgw, tb>>>(Wo, WTh + 3 * D_ * D_, WTl + 3 * D_ * D_, D_, D_);

    // 3) projections (hi/lo out for q,k; fp32 out for v)
    dim3 gproj(D_ / TILE_N, BS_ / TILE_M, 1);
    gemm_mma<<<gproj, 256, SMEM_GEMM>>>(qh, ql, WTh + 0 * D_ * D_, WTl + 0 * D_ * D_,
        D_, D_, 0, 0, 0, 1.f, bq, nullptr, 0, nullptr, qph, qpl);
    gemm_mma<<<gproj, 256, SMEM_GEMM>>>(kh, kl, WTh + 1 * D_ * D_, WTl + 1 * D_ * D_,
        D_, D_, 0, 0, 0, 1.f, bk, nullptr, 0, nullptr, kph, kpl);
    gemm_mma<<<gproj, 256, SMEM_GEMM>>>(vh, vl, WTh + 2 * D_ * D_, WTl + 2 * D_ * D_,
        D_, D_, 0, 0, 0, 1.f, bv, nullptr, 0, vp, nullptr, nullptr);

    // 4) vp [B,S,D] -> vpT [B,D,S] hi/lo
    dim3 tgv(D_ / 32, S_ / 32, B_);
    transpose_hilo<<<tgv, tb>>>(vp, vpTh, vpTl, S_, D_);

    // 5) logits = qp @ kp^T / 16 + mask * -1e9  (fp32 out)
    dim3 glog(S_ / TILE_N, S_ / TILE_M, B_);
    gemm_mma<<<glog, 256, SMEM_GEMM>>>(qph, qpl, kph, kpl,
        S_, D_, (size_t)S_ * D_, (size_t)S_ * D_, (size_t)S_ * S_,
        1.f / 16.f, nullptr, mask, S_, attn_out, nullptr, nullptr);

    // 6) softmax (+ hi/lo emit)
    softmax_kernel<<<B_ * S_, 256>>>(attn_out, ath, atl);

    // 7) ctx = attn @ vp -> hi/lo
    dim3 gpv(D_ / TILE_N, S_ / TILE_M, B_);
    gemm_mma<<<gpv, 256, SMEM_GEMM>>>(ath, atl, vpTh, vpTl,
        D_, S_, (size_t)S_ * S_, (size_t)D_ * S_, (size_t)S_ * D_,
        1.f, nullptr, nullptr, 0, nullptr, ctxh, ctxl);

    // 8) z = ctx @ Wo + bo (fp32 out)
    gemm_mma<<<gproj, 256, SMEM_GEMM>>>(ctxh, ctxl, WTh + 3 * D_ * D_, WTl + 3 * D_ * D_,
        D_, D_, 0, 0, 0, 1.f, bo, nullptr, 0, z_out, nullptr, nullptr);
}

// round 5
// speedup vs baseline: 3.9209x; 1.7439x over previous
#include <cuda_runtime.h>
#include <cuda_bf16.h>
#include <cstdint>
#include <math.h>

#define B_ 4
#define S_ 4096
#define D_ 256
#define BS_ (B_ * S_)

#define TILE_M 128
#define TILE_N 128
#define TILE_K 64

// ---------------- scratch (__device__ globals; no allocs) ----------------
__device__ __nv_bfloat16 g_q_hi[BS_ * D_], g_q_lo[BS_ * D_];
__device__ __nv_bfloat16 g_k_hi[BS_ * D_], g_k_lo[BS_ * D_];
__device__ __nv_bfloat16 g_v_hi[BS_ * D_], g_v_lo[BS_ * D_];
__device__ __nv_bfloat16 g_qp_hi[BS_ * D_], g_qp_lo[BS_ * D_];
__device__ __nv_bfloat16 g_kp_hi[BS_ * D_], g_kp_lo[BS_ * D_];
__device__ float         g_vp[BS_ * D_];
__device__ __nv_bfloat16 g_vpT_hi[BS_ * D_], g_vpT_lo[BS_ * D_];
__device__ __nv_bfloat16 g_ctx_hi[BS_ * D_], g_ctx_lo[BS_ * D_];
__device__ __nv_bfloat16 g_WT_hi[4][D_ * D_], g_WT_lo[4][D_ * D_];
__device__ __nv_bfloat16 g_attn_hi[(size_t)B_ * S_ * S_];
__device__ __nv_bfloat16 g_attn_lo[(size_t)B_ * S_ * S_];
__device__ float         g_attn_f[(size_t)B_ * S_ * S_];   // fallback
__device__ float         g_z[BS_ * D_];                    // fallback

// ---------------- helpers ----------------
__device__ __forceinline__ uint32_t smem_u32(const void* p) {
    uint32_t a;
    asm("{ .reg .u64 t; cvta.to.shared.u64 t, %1; cvt.u32.u64 %0, t; }" : "=r"(a) : "l"(p));
    return a;
}
#define SWZ128(o) ((o) ^ (((o) >> 3) & 0x70))

__device__ __forceinline__ void cpa16(uint32_t s, const void* g) {
    asm volatile("cp.async.cg.shared.global [%0], [%1], 16;" :: "r"(s), "l"(g));
}
#define CP_COMMIT() asm volatile("cp.async.commit_group;")
#define CP_WAIT1()  asm volatile("cp.async.wait_group 1;" ::: "memory")
#define CP_WAIT0()  asm volatile("cp.async.wait_group 0;" ::: "memory")

__device__ __forceinline__ void ldm_x4(uint32_t* r, uint32_t addr) {
    asm volatile("ldmatrix.sync.aligned.m8n8.x4.shared.b16 {%0,%1,%2,%3}, [%4];"
                 : "=r"(r[0]), "=r"(r[1]), "=r"(r[2]), "=r"(r[3]) : "r"(addr));
}
__device__ __forceinline__ void mma16816(float* c, const uint32_t* a, const uint32_t* b) {
    asm volatile("mma.sync.aligned.m16n8k16.row.col.f32.bf16.bf16.f32 "
                 "{%0,%1,%2,%3}, {%4,%5,%6,%7}, {%8,%9}, {%0,%1,%2,%3};"
                 : "+f"(c[0]), "+f"(c[1]), "+f"(c[2]), "+f"(c[3])
                 : "r"(a[0]), "r"(a[1]), "r"(a[2]), "r"(a[3]), "r"(b[0]), "r"(b[1]));
}

__device__ __forceinline__ uint32_t pack_bf2(float a, float b) {
    uint32_t r;
    asm("cvt.rn.bf16x2.f32 %0, %1, %2;" : "=r"(r) : "f"(b), "f"(a));
    return r;
}
__device__ __forceinline__ void residual2(uint32_t h, float a, float b, float& ra, float& rb) {
    ra = a - __uint_as_float(h << 16);
    rb = b - __uint_as_float(h & 0xffff0000u);
}

// ----------------------------------------------------------------------------
// mma.sync bf16x3 GEMM:  C[z] = alpha * A[z] @ B[z]^T (+bias) (+causal)
// A: [M,K] hi/lo bf16 row-major; B: [N,K] hi/lo bf16 row-major
// cmode: 0 = plain, 1 = logits (skip upper-tri tiles, causal -1e9 epilogue),
//        2 = PV (K-chunks limited to causal prefix of the m-tile)
// ----------------------------------------------------------------------------
#define OFF_AH 0
#define OFF_AL 16384
#define OFF_BH 32768
#define OFF_BL 49152
#define STAGE_B 65536
#define SMEM_GEMM (2 * STAGE_B)

__device__ __forceinline__ void tile_cp(uint32_t sbase, const __nv_bfloat16* g,
                                        size_t ldK, int tid) {
#pragma unroll
    for (int i = 0; i < 4; i++) {
        int u = tid + (i << 8);
        int r = u >> 3, c = u & 7;
        uint32_t off = (uint32_t)(r * 128 + c * 16);
        cpa16(sbase + SWZ128(off), (const char*)(g + (size_t)r * ldK) + (c << 4));
    }
}

__global__ __launch_bounds__(256, 1)
void gemm_mma(const __nv_bfloat16* __restrict__ Ahi, const __nv_bfloat16* __restrict__ Alo,
              const __nv_bfloat16* __restrict__ Bhi, const __nv_bfloat16* __restrict__ Blo,
              int N, int K,
              size_t sA, size_t sB, size_t sC,
              float alpha, const float* __restrict__ bias, int cmode,
              float* __restrict__ Cf,
              __nv_bfloat16* __restrict__ Chi, __nv_bfloat16* __restrict__ Clo)
{
    const int m0 = blockIdx.y * TILE_M;
    const int n0 = blockIdx.x * TILE_N;
    if (cmode == 1 && n0 > m0) return;   // fully-masked logits tile

    extern __shared__ char dsm[];
    const uint32_t sb = smem_u32(dsm);
    const int tid = threadIdx.x;
    const int wid = tid >> 5;
    const int lane = tid & 31;

    const int z = blockIdx.z;
    Ahi += (size_t)z * sA; Alo += (size_t)z * sA;
    Bhi += (size_t)z * sB; Blo += (size_t)z * sB;
    if (Cf)  Cf  += (size_t)z * sC;
    if (Chi) { Chi += (size_t)z * sC; Clo += (size_t)z * sC; }

    const int mrow0 = (wid & 1) * 64;
    const int ncol0 = (wid >> 1) * 32;

    const __nv_bfloat16* aH = Ahi + (size_t)m0 * K;
    const __nv_bfloat16* aL = Alo + (size_t)m0 * K;
    const __nv_bfloat16* bH = Bhi + (size_t)n0 * K;
    const __nv_bfloat16* bL = Blo + (size_t)n0 * K;

    float acc[4][4][4];
#pragma unroll
    for (int i = 0; i < 4; i++)
#pragma unroll
        for (int j = 0; j < 4; j++)
#pragma unroll
            for (int l = 0; l < 4; l++) acc[i][j][l] = 0.f;

    int NC = K / TILE_K;
    if (cmode == 2) {                    // causal prefix: chunks < (m0+128)/64
        int nc2 = (m0 >> 6) + 2;
        if (nc2 < NC) NC = nc2;
    }

    {
        const uint32_t st = sb;
        tile_cp(st + OFF_AH, aH, K, tid);
        tile_cp(st + OFF_AL, aL, K, tid);
        tile_cp(st + OFF_BH, bH, K, tid);
        tile_cp(st + OFF_BL, bL, K, tid);
        CP_COMMIT();
    }

    const uint32_t lane15 = (uint32_t)(lane & 15);
    const uint32_t khalf = (uint32_t)((lane >> 4) << 4);

    for (int c = 0; c < NC; c++) {
        if (c + 1 < NC) {
            const uint32_t st = sb + ((c + 1) & 1) * STAGE_B;
            const size_t ko = (size_t)(c + 1) * TILE_K;
            tile_cp(st + OFF_AH, aH + ko, K, tid);
            tile_cp(st + OFF_AL, aL + ko, K, tid);
            tile_cp(st + OFF_BH, bH + ko, K, tid);
            tile_cp(st + OFF_BL, bL + ko, K, tid);
            CP_COMMIT();
            CP_WAIT1();
        } else {
            CP_WAIT0();
        }
        __syncthreads();

        const uint32_t st = sb + (c & 1) * STAGE_B;
        const uint32_t sAh = st + OFF_AH, sAl = st + OFF_AL;
        const uint32_t sBh = st + OFF_BH, sBl = st + OFF_BL;

#pragma unroll
        for (int ks = 0; ks < 4; ks++) {
            const uint32_t kb = (uint32_t)(ks * 32) + khalf;
            uint32_t ah[4][4], al[4][4], bh[4][2], bl[4][2];
#pragma unroll
            for (int mt = 0; mt < 4; mt++) {
                const uint32_t ro = (uint32_t)(mrow0 + mt * 16) + lane15;
                ldm_x4(ah[mt], sAh + SWZ128(ro * 128 + kb));
                ldm_x4(al[mt], sAl + SWZ128(ro * 128 + kb));
            }
#pragma unroll
            for (int g = 0; g < 2; g++) {
                const uint32_t ro = (uint32_t)(ncol0 + g * 16) + lane15;
                uint32_t t4[4];
                ldm_x4(t4, sBh + SWZ128(ro * 128 + kb));
                bh[g * 2][0] = t4[0]; bh[g * 2][1] = t4[2];
                bh[g * 2 + 1][0] = t4[1]; bh[g * 2 + 1][1] = t4[3];
                ldm_x4(t4, sBl + SWZ128(ro * 128 + kb));
                bl[g * 2][0] = t4[0]; bl[g * 2][1] = t4[2];
                bl[g * 2 + 1][0] = t4[1]; bl[g * 2 + 1][1] = t4[3];
            }
#pragma unroll
            for (int mt = 0; mt < 4; mt++)
#pragma unroll
                for (int nt = 0; nt < 4; nt++) {
                    mma16816(acc[mt][nt], ah[mt], bh[nt]);
                    mma16816(acc[mt][nt], ah[mt], bl[nt]);
                    mma16816(acc[mt][nt], al[mt], bh[nt]);
                }
        }
        __syncthreads();
    }

    // ---- epilogue ----
    float* stg = (float*)dsm;
    const int ELD = 132;
    const int rr = lane >> 2;
    const int cc = (lane & 3) * 2;
#pragma unroll
    for (int mt = 0; mt < 4; mt++)
#pragma unroll
        for (int nt = 0; nt < 4; nt++) {
            const int r = mrow0 + mt * 16 + rr;
            const int cn = ncol0 + nt * 8 + cc;
            stg[r * ELD + cn]           = acc[mt][nt][0];
            stg[r * ELD + cn + 1]       = acc[mt][nt][1];
            stg[(r + 8) * ELD + cn]     = acc[mt][nt][2];
            stg[(r + 8) * ELD + cn + 1] = acc[mt][nt][3];
        }
    __syncthreads();

#pragma unroll 1
    for (int it = 0; it < 16; it++) {
        const int u = tid + (it << 8);
        const int r = u >> 5;
        const int f = (u & 31) << 2;
        const float* s = stg + r * ELD + f;
        float v0 = s[0] * alpha, v1 = s[1] * alpha, v2 = s[2] * alpha, v3 = s[3] * alpha;
        const int n = n0 + f;
        const int mi = m0 + r;
        const size_t m = (size_t)mi;
        if (bias) {
            float4 bv = *(const float4*)(bias + n);
            v0 += bv.x; v1 += bv.y; v2 += bv.z; v3 += bv.w;
        }
        if (cmode == 1) {               // causal additive mask (exact)
            if (n + 0 > mi) v0 += -1e9f;
            if (n + 1 > mi) v1 += -1e9f;
            if (n + 2 > mi) v2 += -1e9f;
            if (n + 3 > mi) v3 += -1e9f;
        }
        const size_t o = m * (size_t)N + n;
        if (Cf) {
            float4 ov = {v0, v1, v2, v3};
            *(float4*)(Cf + o) = ov;
        }
        if (Chi) {
            uint32_t h0 = pack_bf2(v0, v1), h1 = pack_bf2(v2, v3);
            float r0, r1, r2, r3;
            residual2(h0, v0, v1, r0, r1);
            residual2(h1, v2, v3, r2, r3);
            uint2 hv = {h0, h1};
            uint2 lv = {pack_bf2(r0, r1), pack_bf2(r2, r3)};
            *(uint2*)(Chi + o) = hv;
            *(uint2*)(Clo + o) = lv;
        }
    }
}

// ---------------- fp32 -> (hi, lo) bf16 ----------------
__global__ __launch_bounds__(256)
void convert_hilo(const float* __restrict__ in, __nv_bfloat16* __restrict__ hi,
                  __nv_bfloat16* __restrict__ lo, int n4)
{
    int i = blockIdx.x * blockDim.x + threadIdx.x;
    if (i >= n4) return;
    float4 v = ((const float4*)in)[i];
    uint32_t h0 = pack_bf2(v.x, v.y), h1 = pack_bf2(v.z, v.w);
    float r0, r1, r2, r3;
    residual2(h0, v.x, v.y, r0, r1);
    residual2(h1, v.z, v.w, r2, r3);
    uint2 hv = {h0, h1};
    uint2 lv = {pack_bf2(r0, r1), pack_bf2(r2, r3)};
    ((uint2*)hi)[i] = hv;
    ((uint2*)lo)[i] = lv;
}

// ---------------- transpose + split ----------------
__global__ __launch_bounds__(256)
void transpose_hilo(const float* __restrict__ in, __nv_bfloat16* __restrict__ ohi,
                    __nv_bfloat16* __restrict__ olo, int R, int C)
{
    __shared__ float t[32][33];
    const int z = blockIdx.z;
    in  += (size_t)z * R * C;
    ohi += (size_t)z * R * C;
    olo += (size_t)z * R * C;
    const int r0 = blockIdx.y * 32, c0 = blockIdx.x * 32;
    const int tx = threadIdx.x, ty = threadIdx.y;
#pragma unroll
    for (int j = 0; j < 32; j += 8)
        t[ty + j][tx] = in[(size_t)(r0 + ty + j) * C + c0 + tx];
    __syncthreads();
#pragma unroll
    for (int j = 0; j < 32; j += 8) {
        float v = t[tx][ty + j];
        __nv_bfloat16 h = __float2bfloat16(v);
        __nv_bfloat16 l = __float2bfloat16(v - __bfloat162float(h));
        size_t o = (size_t)(c0 + ty + j) * R + r0 + tx;
        ohi[o] = h; olo[o] = l;
    }
}

// ---------------- causal softmax: prefix m+1 only, zero-fill tail ----------------
__global__ __launch_bounds__(256)
void softmax_kernel(float* __restrict__ attn, __nv_bfloat16* __restrict__ ahi,
                    __nv_bfloat16* __restrict__ alo)
{
    __shared__ float buf[S_];
    __shared__ float red[8];
    __shared__ float s_max, s_sum;

    const size_t rb = (size_t)blockIdx.x * S_;
    float* row = attn + rb;
    const int t = threadIdx.x;
    const int m = blockIdx.x & (S_ - 1);
    const int L = m + 1;
    const int L4 = (L + 3) & ~3;
    const int Lpad = ((m >> 7) + 1) << 7;     // hi/lo needed up to here
    const float NINF = __int_as_float(0xff800000);

    float mx = -1e30f;
    for (int i = t * 4; i < L4; i += 1024) {
        float4 v = *(const float4*)(row + i);
        if (i + 0 >= L) v.x = NINF;
        if (i + 1 >= L) v.y = NINF;
        if (i + 2 >= L) v.z = NINF;
        if (i + 3 >= L) v.w = NINF;
        *(float4*)(buf + i) = v;
        mx = fmaxf(mx, fmaxf(fmaxf(v.x, v.y), fmaxf(v.z, v.w)));
    }
#pragma unroll
    for (int o = 16; o; o >>= 1) mx = fmaxf(mx, __shfl_xor_sync(0xffffffffu, mx, o));
    if ((t & 31) == 0) red[t >> 5] = mx;
    __syncthreads();
    if (t == 0) {
        float v = red[0];
#pragma unroll
        for (int i = 1; i < 8; i++) v = fmaxf(v, red[i]);
        s_max = v;
    }
    __syncthreads();
    const float mxv = s_max;

    float sum = 0.f;
    for (int i = t * 4; i < L4; i += 1024) {
        float4 v = *(const float4*)(buf + i);
        v.x = __expf(v.x - mxv); v.y = __expf(v.y - mxv);
        v.z = __expf(v.z - mxv); v.w = __expf(v.w - mxv);
        *(float4*)(buf + i) = v;
        sum += v.x + v.y + v.z + v.w;
    }
#pragma unroll
    for (int o = 16; o; o >>= 1) sum += __shfl_xor_sync(0xffffffffu, sum, o);
    if ((t & 31) == 0) red[t >> 5] = sum;
    __syncthreads();
    if (t == 0) {
        float v = red[0];
#pragma unroll
        for (int i = 1; i < 8; i++) v += red[i];
        s_sum = v;
    }
    __syncthreads();
    const float inv = 1.f / s_sum;

    for (int i = t * 4; i < L4; i += 1024) {
        float4 v = *(const float4*)(buf + i);
        v.x *= inv; v.y *= inv; v.z *= inv; v.w *= inv;
        *(float4*)(row + i) = v;
        uint32_t h0 = pack_bf2(v.x, v.y), h1 = pack_bf2(v.z, v.w);
        float r0, r1, r2, r3;
        residual2(h0, v.x, v.y, r0, r1);
        residual2(h1, v.z, v.w, r2, r3);
        uint2 hv = {h0, h1};
        uint2 lv = {pack_bf2(r0, r1), pack_bf2(r2, r3)};
        *(uint2*)(ahi + rb + i) = hv;
        *(uint2*)(alo + rb + i) = lv;
    }
    // tails: fp32 zeros to S_, hi/lo zeros to Lpad
    const uint2 z2 = {0u, 0u};
    const float4 z4 = {0.f, 0.f, 0.f, 0.f};
    for (int i = L4 + t * 4; i < S_; i += 1024) {
        *(float4*)(row + i) = z4;
        if (i < Lpad) {
            *(uint2*)(ahi + rb + i) = z2;
            *(uint2*)(alo + rb + i) = z2;
        }
    }
}

// ---------------- launch ----------------
extern "C" void kernel_launch(void* const* d_in, const int* in_sizes, int n_in,
                              void* d_out, int out_size)
{
    const float* q    = (const float*)d_in[0];
    const float* k    = (const float*)d_in[1];
    const float* v    = (const float*)d_in[2];
    const float* Wq   = (const float*)d_in[4];
    const float* bq   = (const float*)d_in[5];
    const float* Wk   = (const float*)d_in[6];
    const float* bk   = (const float*)d_in[7];
    const float* Wv   = (const float*)d_in[8];
    const float* bv   = (const float*)d_in[9];
    const float* Wo   = (const float*)d_in[10];
    const float* bo   = (const float*)d_in[11];

#define SYM(p, s) cudaGetSymbolAddress((void**)&p, s)
    __nv_bfloat16 *qh, *ql, *kh, *kl, *vh, *vl;
    __nv_bfloat16 *qph, *qpl, *kph, *kpl, *vpTh, *vpTl, *ctxh, *ctxl, *ath, *atl;
    __nv_bfloat16 *WTh, *WTl;
    float *vp, *attn_scr, *z_scr;
    SYM(qh, g_q_hi);  SYM(ql, g_q_lo);
    SYM(kh, g_k_hi);  SYM(kl, g_k_lo);
    SYM(vh, g_v_hi);  SYM(vl, g_v_lo);
    SYM(qph, g_qp_hi); SYM(qpl, g_qp_lo);
    SYM(kph, g_kp_hi); SYM(kpl, g_kp_lo);
    SYM(vp, g_vp);
    SYM(vpTh, g_vpT_hi); SYM(vpTl, g_vpT_lo);
    SYM(ctxh, g_ctx_hi); SYM(ctxl, g_ctx_lo);
    SYM(ath, g_attn_hi); SYM(atl, g_attn_lo);
    SYM(WTh, (g_WT_hi[0][0]));   SYM(WTl, (g_WT_lo[0][0]));
    SYM(attn_scr, g_attn_f); SYM(z_scr, g_z);

    const size_t zN = (size_t)BS_ * D_;
    const size_t aN = (size_t)B_ * S_ * S_;
    float* out = (float*)d_out;
    float *z_out, *attn_out;
    if ((size_t)out_size >= zN + aN) { z_out = out; attn_out = out + zN; }
    else if ((size_t)out_size == aN) { attn_out = out; z_out = z_scr; }
    else                             { z_out = out; attn_out = attn_scr; }

    cudaFuncSetAttribute(gemm_mma, cudaFuncAttributeMaxDynamicSharedMemorySize, SMEM_GEMM);

    // 1) split inputs
    const int n4 = BS_ * D_ / 4;
    convert_hilo<<<(n4 + 255) / 256, 256>>>(q, qh, ql, n4);
    convert_hilo<<<(n4 + 255) / 256, 256>>>(k, kh, kl, n4);
    convert_hilo<<<(n4 + 255) / 256, 256>>>(v, vh, vl, n4);

    // 2) transpose+split weights: W [K,N] -> WT [N,K]
    dim3 tb(32, 8);
    dim3 tgw(D_ / 32, D_ / 32, 1);
    transpose_hilo<<<tgw, tb>>>(Wq, WTh + 0 * D_ * D_, WTl + 0 * D_ * D_, D_, D_);
    transpose_hilo<<<tgw, tb>>>(Wk, WTh + 1 * D_ * D_, WTl + 1 * D_ * D_, D_, D_);
    transpose_hilo<<<tgw, tb>>>(Wv, WTh + 2 * D_ * D_, WTl + 2 * D_ * D_, D_, D_);
    transpose_hilo<<<tgw, tb>>>(Wo, WTh + 3 * D_ * D_, WTl + 3 * D_ * D_, D_, D_);

    // 3) projections
    dim3 gproj(D_ / TILE_N, BS_ / TILE_M, 1);
    gemm_mma<<<gproj, 256, SMEM_GEMM>>>(qh, ql, WTh + 0 * D_ * D_, WTl + 0 * D_ * D_,
        D_, D_, 0, 0, 0, 1.f, bq, 0, nullptr, qph, qpl);
    gemm_mma<<<gproj, 256, SMEM_GEMM>>>(kh, kl, WTh + 1 * D_ * D_, WTl + 1 * D_ * D_,
        D_, D_, 0, 0, 0, 1.f, bk, 0, nullptr, kph, kpl);
    gemm_mma<<<gproj, 256, SMEM_GEMM>>>(vh, vl, WTh + 2 * D_ * D_, WTl + 2 * D_ * D_,
        D_, D_, 0, 0, 0, 1.f, bv, 0, vp, nullptr, nullptr);

    // 4) vp [B,S,D] -> vpT [B,D,S] hi/lo
    dim3 tgv(D_ / 32, S_ / 32, B_);
    transpose_hilo<<<tgv, tb>>>(vp, vpTh, vpTl, S_, D_);

    // 5) logits = qp @ kp^T / 16 + causal  (fp32 out; lower-triangle tiles only)
    dim3 glog(S_ / TILE_N, S_ / TILE_M, B_);
    gemm_mma<<<glog, 256, SMEM_GEMM>>>(qph, qpl, kph, kpl,
        S_, D_, (size_t)S_ * D_, (size_t)S_ * D_, (size_t)S_ * S_,
        1.f / 16.f, nullptr, 1, attn_out, nullptr, nullptr);

    // 6) causal softmax (+ hi/lo emit over prefix)
    softmax_kernel<<<B_ * S_, 256>>>(attn_out, ath, atl);

    // 7) ctx = attn @ vp -> hi/lo  (causal K-prefix)
    dim3 gpv(D_ / TILE_N, S_ / TILE_M, B_);
    gemm_mma<<<gpv, 256, SMEM_GEMM>>>(ath, atl, vpTh, vpTl,
        D_, S_, (size_t)S_ * S_, (size_t)D_ * S_, (size_t)S_ * D_,
        1.f, nullptr, 2, nullptr, ctxh, ctxl);

    // 8) z = ctx @ Wo + bo (fp32 out)
    gemm_mma<<<gproj, 256, SMEM_GEMM>>>(ctxh, ctxl, WTh + 3 * D_ * D_, WTl + 3 * D_ * D_,
        D_, D_, 0, 0, 0, 1.f, bo, 0, z_out, nullptr, nullptr);
}

// round 6
// speedup vs baseline: 4.1670x; 1.0627x over previous
#include <cuda_runtime.h>
#include <cuda_bf16.h>
#include <cstdint>
#include <math.h>

#define B_ 4
#define S_ 4096
#define D_ 256
#define BS_ (B_ * S_)

#define TILE_M 128
#define TILE_N 128
#define TILE_K 64

// ---------------- scratch (__device__ globals; no allocs) ----------------
__device__ __nv_bfloat16 g_q_hi[BS_ * D_], g_q_lo[BS_ * D_];
__device__ __nv_bfloat16 g_k_hi[BS_ * D_], g_k_lo[BS_ * D_];
__device__ __nv_bfloat16 g_v_hi[BS_ * D_], g_v_lo[BS_ * D_];
__device__ __nv_bfloat16 g_qp_hi[BS_ * D_], g_qp_lo[BS_ * D_];
__device__ __nv_bfloat16 g_kp_hi[BS_ * D_], g_kp_lo[BS_ * D_];
__device__ float         g_vp[BS_ * D_];
__device__ __nv_bfloat16 g_vpT_hi[BS_ * D_], g_vpT_lo[BS_ * D_];
__device__ __nv_bfloat16 g_ctx_hi[BS_ * D_], g_ctx_lo[BS_ * D_];
__device__ __nv_bfloat16 g_WT_hi[4][D_ * D_], g_WT_lo[4][D_ * D_];
__device__ __nv_bfloat16 g_attn_hi[(size_t)B_ * S_ * S_];
__device__ __nv_bfloat16 g_attn_lo[(size_t)B_ * S_ * S_];
__device__ float         g_attn_f[(size_t)B_ * S_ * S_];   // fallback
__device__ float         g_z[BS_ * D_];                    // fallback

// ---------------- helpers ----------------
__device__ __forceinline__ uint32_t smem_u32(const void* p) {
    uint32_t a;
    asm("{ .reg .u64 t; cvta.to.shared.u64 t, %1; cvt.u32.u64 %0, t; }" : "=r"(a) : "l"(p));
    return a;
}
#define SWZ128(o) ((o) ^ (((o) >> 3) & 0x70))

__device__ __forceinline__ void cpa16(uint32_t s, const void* g) {
    asm volatile("cp.async.cg.shared.global [%0], [%1], 16;" :: "r"(s), "l"(g));
}
#define CP_COMMIT() asm volatile("cp.async.commit_group;")
#define CP_WAIT1()  asm volatile("cp.async.wait_group 1;" ::: "memory")
#define CP_WAIT0()  asm volatile("cp.async.wait_group 0;" ::: "memory")

__device__ __forceinline__ void ldm_x4(uint32_t* r, uint32_t addr) {
    asm volatile("ldmatrix.sync.aligned.m8n8.x4.shared.b16 {%0,%1,%2,%3}, [%4];"
                 : "=r"(r[0]), "=r"(r[1]), "=r"(r[2]), "=r"(r[3]) : "r"(addr));
}
__device__ __forceinline__ void mma16816(float* c, const uint32_t* a, const uint32_t* b) {
    asm volatile("mma.sync.aligned.m16n8k16.row.col.f32.bf16.bf16.f32 "
                 "{%0,%1,%2,%3}, {%4,%5,%6,%7}, {%8,%9}, {%0,%1,%2,%3};"
                 : "+f"(c[0]), "+f"(c[1]), "+f"(c[2]), "+f"(c[3])
                 : "r"(a[0]), "r"(a[1]), "r"(a[2]), "r"(a[3]), "r"(b[0]), "r"(b[1]));
}

__device__ __forceinline__ uint32_t pack_bf2(float a, float b) {
    uint32_t r;
    asm("cvt.rn.bf16x2.f32 %0, %1, %2;" : "=r"(r) : "f"(b), "f"(a));
    return r;
}
__device__ __forceinline__ void residual2(uint32_t h, float a, float b, float& ra, float& rb) {
    ra = a - __uint_as_float(h << 16);
    rb = b - __uint_as_float(h & 0xffff0000u);
}

// ----------------------------------------------------------------------------
// mma.sync bf16x3 GEMM:  C[z] = alpha * A[z] @ B[z]^T (+bias) (+causal)
// 512 threads, 16 warps (4x4 warp grid, 32x32 warp tile), CTA tile 128x128x64.
// cmode: 0 plain, 1 logits (skip upper-tri, causal epilogue), 2 PV (K-prefix,
//        reversed m order for load balance)
// ----------------------------------------------------------------------------
#define OFF_AH 0
#define OFF_AL 16384
#define OFF_BH 32768
#define OFF_BL 49152
#define STAGE_B 65536
#define SMEM_GEMM (2 * STAGE_B)

__device__ __forceinline__ void tile_cp(uint32_t sbase, const __nv_bfloat16* g,
                                        size_t ldK, int tid) {
#pragma unroll
    for (int i = 0; i < 2; i++) {
        int u = tid + (i << 9);
        int r = u >> 3, c = u & 7;
        uint32_t off = (uint32_t)(r * 128 + c * 16);
        cpa16(sbase + SWZ128(off), (const char*)(g + (size_t)r * ldK) + (c << 4));
    }
}

__global__ __launch_bounds__(512, 1)
void gemm_mma(const __nv_bfloat16* __restrict__ Ahi, const __nv_bfloat16* __restrict__ Alo,
              const __nv_bfloat16* __restrict__ Bhi, const __nv_bfloat16* __restrict__ Blo,
              int N, int K,
              size_t sA, size_t sB, size_t sC,
              float alpha, const float* __restrict__ bias, int cmode,
              float* __restrict__ Cf,
              __nv_bfloat16* __restrict__ Chi, __nv_bfloat16* __restrict__ Clo)
{
    int by = blockIdx.y;
    if (cmode == 2) by = gridDim.y - 1 - by;   // heavy tiles first
    const int m0 = by * TILE_M;
    const int n0 = blockIdx.x * TILE_N;
    if (cmode == 1 && n0 > m0) return;         // fully-masked logits tile

    extern __shared__ char dsm[];
    const uint32_t sb = smem_u32(dsm);
    const int tid = threadIdx.x;
    const int wid = tid >> 5;
    const int lane = tid & 31;

    const int z = blockIdx.z;
    Ahi += (size_t)z * sA; Alo += (size_t)z * sA;
    Bhi += (size_t)z * sB; Blo += (size_t)z * sB;
    if (Cf)  Cf  += (size_t)z * sC;
    if (Chi) { Chi += (size_t)z * sC; Clo += (size_t)z * sC; }

    const int mrow0 = (wid & 3) * 32;          // 4 warp-rows
    const int ncol0 = (wid >> 2) * 32;         // 4 warp-cols

    const __nv_bfloat16* aH = Ahi + (size_t)m0 * K;
    const __nv_bfloat16* aL = Alo + (size_t)m0 * K;
    const __nv_bfloat16* bH = Bhi + (size_t)n0 * K;
    const __nv_bfloat16* bL = Blo + (size_t)n0 * K;

    float acc[2][4][4];
#pragma unroll
    for (int i = 0; i < 2; i++)
#pragma unroll
        for (int j = 0; j < 4; j++)
#pragma unroll
            for (int l = 0; l < 4; l++) acc[i][j][l] = 0.f;

    int NC = K / TILE_K;
    if (cmode == 2) {                          // causal prefix
        int nc2 = (m0 >> 6) + 2;
        if (nc2 < NC) NC = nc2;
    }

    {
        const uint32_t st = sb;
        tile_cp(st + OFF_AH, aH, K, tid);
        tile_cp(st + OFF_AL, aL, K, tid);
        tile_cp(st + OFF_BH, bH, K, tid);
        tile_cp(st + OFF_BL, bL, K, tid);
        CP_COMMIT();
    }

    const uint32_t lane15 = (uint32_t)(lane & 15);
    const uint32_t khalf = (uint32_t)((lane >> 4) << 4);

    for (int c = 0; c < NC; c++) {
        if (c + 1 < NC) {
            const uint32_t st = sb + ((c + 1) & 1) * STAGE_B;
            const size_t ko = (size_t)(c + 1) * TILE_K;
            tile_cp(st + OFF_AH, aH + ko, K, tid);
            tile_cp(st + OFF_AL, aL + ko, K, tid);
            tile_cp(st + OFF_BH, bH + ko, K, tid);
            tile_cp(st + OFF_BL, bL + ko, K, tid);
            CP_COMMIT();
            CP_WAIT1();
        } else {
            CP_WAIT0();
        }
        __syncthreads();

        const uint32_t st = sb + (c & 1) * STAGE_B;
        const uint32_t sAh = st + OFF_AH, sAl = st + OFF_AL;
        const uint32_t sBh = st + OFF_BH, sBl = st + OFF_BL;

#pragma unroll
        for (int ks = 0; ks < 4; ks++) {
            const uint32_t kb = (uint32_t)(ks * 32) + khalf;
            uint32_t ah[2][4], al[2][4], bh[4][2], bl[4][2];
#pragma unroll
            for (int mt = 0; mt < 2; mt++) {
                const uint32_t ro = (uint32_t)(mrow0 + mt * 16) + lane15;
                ldm_x4(ah[mt], sAh + SWZ128(ro * 128 + kb));
                ldm_x4(al[mt], sAl + SWZ128(ro * 128 + kb));
            }
#pragma unroll
            for (int g = 0; g < 2; g++) {
                const uint32_t ro = (uint32_t)(ncol0 + g * 16) + lane15;
                uint32_t t4[4];
                ldm_x4(t4, sBh + SWZ128(ro * 128 + kb));
                bh[g * 2][0] = t4[0]; bh[g * 2][1] = t4[2];
                bh[g * 2 + 1][0] = t4[1]; bh[g * 2 + 1][1] = t4[3];
                ldm_x4(t4, sBl + SWZ128(ro * 128 + kb));
                bl[g * 2][0] = t4[0]; bl[g * 2][1] = t4[2];
                bl[g * 2 + 1][0] = t4[1]; bl[g * 2 + 1][1] = t4[3];
            }
#pragma unroll
            for (int mt = 0; mt < 2; mt++)
#pragma unroll
                for (int nt = 0; nt < 4; nt++) {
                    mma16816(acc[mt][nt], ah[mt], bh[nt]);
                    mma16816(acc[mt][nt], ah[mt], bl[nt]);
                    mma16816(acc[mt][nt], al[mt], bh[nt]);
                }
        }
        __syncthreads();
    }

    // ---- epilogue: regs -> smem stage -> coalesced gmem ----
    float* stg = (float*)dsm;
    const int ELD = 132;
    const int rr = lane >> 2;
    const int cc = (lane & 3) * 2;
#pragma unroll
    for (int mt = 0; mt < 2; mt++)
#pragma unroll
        for (int nt = 0; nt < 4; nt++) {
            const int r = mrow0 + mt * 16 + rr;
            const int cn = ncol0 + nt * 8 + cc;
            stg[r * ELD + cn]           = acc[mt][nt][0];
            stg[r * ELD + cn + 1]       = acc[mt][nt][1];
            stg[(r + 8) * ELD + cn]     = acc[mt][nt][2];
            stg[(r + 8) * ELD + cn + 1] = acc[mt][nt][3];
        }
    __syncthreads();

#pragma unroll 1
    for (int it = 0; it < 8; it++) {
        const int u = tid + (it << 9);
        const int r = u >> 5;
        const int f = (u & 31) << 2;
        const float* s = stg + r * ELD + f;
        float v0 = s[0] * alpha, v1 = s[1] * alpha, v2 = s[2] * alpha, v3 = s[3] * alpha;
        const int n = n0 + f;
        const int mi = m0 + r;
        const size_t m = (size_t)mi;
        if (bias) {
            float4 bv = *(const float4*)(bias + n);
            v0 += bv.x; v1 += bv.y; v2 += bv.z; v3 += bv.w;
        }
        if (cmode == 1) {
            if (n + 0 > mi) v0 += -1e9f;
            if (n + 1 > mi) v1 += -1e9f;
            if (n + 2 > mi) v2 += -1e9f;
            if (n + 3 > mi) v3 += -1e9f;
        }
        const size_t o = m * (size_t)N + n;
        if (Cf) {
            float4 ov = {v0, v1, v2, v3};
            *(float4*)(Cf + o) = ov;
        }
        if (Chi) {
            uint32_t h0 = pack_bf2(v0, v1), h1 = pack_bf2(v2, v3);
            float r0, r1, r2, r3;
            residual2(h0, v0, v1, r0, r1);
            residual2(h1, v2, v3, r2, r3);
            uint2 hv = {h0, h1};
            uint2 lv = {pack_bf2(r0, r1), pack_bf2(r2, r3)};
            *(uint2*)(Chi + o) = hv;
            *(uint2*)(Clo + o) = lv;
        }
    }
}

// ---------------- fp32 -> (hi, lo) bf16 ----------------
__global__ __launch_bounds__(256)
void convert_hilo(const float* __restrict__ in, __nv_bfloat16* __restrict__ hi,
                  __nv_bfloat16* __restrict__ lo, int n4)
{
    int i = blockIdx.x * blockDim.x + threadIdx.x;
    if (i >= n4) return;
    float4 v = ((const float4*)in)[i];
    uint32_t h0 = pack_bf2(v.x, v.y), h1 = pack_bf2(v.z, v.w);
    float r0, r1, r2, r3;
    residual2(h0, v.x, v.y, r0, r1);
    residual2(h1, v.z, v.w, r2, r3);
    uint2 hv = {h0, h1};
    uint2 lv = {pack_bf2(r0, r1), pack_bf2(r2, r3)};
    ((uint2*)hi)[i] = hv;
    ((uint2*)lo)[i] = lv;
}

// ---------------- transpose + split ----------------
__global__ __launch_bounds__(256)
void transpose_hilo(const float* __restrict__ in, __nv_bfloat16* __restrict__ ohi,
                    __nv_bfloat16* __restrict__ olo, int R, int C)
{
    __shared__ float t[32][33];
    const int z = blockIdx.z;
    in  += (size_t)z * R * C;
    ohi += (size_t)z * R * C;
    olo += (size_t)z * R * C;
    const int r0 = blockIdx.y * 32, c0 = blockIdx.x * 32;
    const int tx = threadIdx.x, ty = threadIdx.y;
#pragma unroll
    for (int j = 0; j < 32; j += 8)
        t[ty + j][tx] = in[(size_t)(r0 + ty + j) * C + c0 + tx];
    __syncthreads();
#pragma unroll
    for (int j = 0; j < 32; j += 8) {
        float v = t[tx][ty + j];
        __nv_bfloat16 h = __float2bfloat16(v);
        __nv_bfloat16 l = __float2bfloat16(v - __bfloat162float(h));
        size_t o = (size_t)(c0 + ty + j) * R + r0 + tx;
        ohi[o] = h; olo[o] = l;
    }
}

// ---------------- causal softmax: prefix m+1 only, zero-fill tail ----------------
__global__ __launch_bounds__(256)
void softmax_kernel(float* __restrict__ attn, __nv_bfloat16* __restrict__ ahi,
                    __nv_bfloat16* __restrict__ alo)
{
    __shared__ float buf[S_];
    __shared__ float red[8];
    __shared__ float s_max, s_sum;

    const size_t rb = (size_t)blockIdx.x * S_;
    float* row = attn + rb;
    const int t = threadIdx.x;
    const int m = blockIdx.x & (S_ - 1);
    const int L = m + 1;
    const int L4 = (L + 3) & ~3;
    const int Lpad = ((m >> 7) + 1) << 7;
    const float NINF = __int_as_float(0xff800000);

    float mx = -1e30f;
    for (int i = t * 4; i < L4; i += 1024) {
        float4 v = *(const float4*)(row + i);
        if (i + 0 >= L) v.x = NINF;
        if (i + 1 >= L) v.y = NINF;
        if (i + 2 >= L) v.z = NINF;
        if (i + 3 >= L) v.w = NINF;
        *(float4*)(buf + i) = v;
        mx = fmaxf(mx, fmaxf(fmaxf(v.x, v.y), fmaxf(v.z, v.w)));
    }
#pragma unroll
    for (int o = 16; o; o >>= 1) mx = fmaxf(mx, __shfl_xor_sync(0xffffffffu, mx, o));
    if ((t & 31) == 0) red[t >> 5] = mx;
    __syncthreads();
    if (t == 0) {
        float v = red[0];
#pragma unroll
        for (int i = 1; i < 8; i++) v = fmaxf(v, red[i]);
        s_max = v;
    }
    __syncthreads();
    const float mxv = s_max;

    float sum = 0.f;
    for (int i = t * 4; i < L4; i += 1024) {
        float4 v = *(const float4*)(buf + i);
        v.x = __expf(v.x - mxv); v.y = __expf(v.y - mxv);
        v.z = __expf(v.z - mxv); v.w = __expf(v.w - mxv);
        *(float4*)(buf + i) = v;
        sum += v.x + v.y + v.z + v.w;
    }
#pragma unroll
    for (int o = 16; o; o >>= 1) sum += __shfl_xor_sync(0xffffffffu, sum, o);
    if ((t & 31) == 0) red[t >> 5] = sum;
    __syncthreads();
    if (t == 0) {
        float v = red[0];
#pragma unroll
        for (int i = 1; i < 8; i++) v += red[i];
        s_sum = v;
    }
    __syncthreads();
    const float inv = 1.f / s_sum;

    for (int i = t * 4; i < L4; i += 1024) {
        float4 v = *(const float4*)(buf + i);
        v.x *= inv; v.y *= inv; v.z *= inv; v.w *= inv;
        *(float4*)(row + i) = v;
        uint32_t h0 = pack_bf2(v.x, v.y), h1 = pack_bf2(v.z, v.w);
        float r0, r1, r2, r3;
        residual2(h0, v.x, v.y, r0, r1);
        residual2(h1, v.z, v.w, r2, r3);
        uint2 hv = {h0, h1};
        uint2 lv = {pack_bf2(r0, r1), pack_bf2(r2, r3)};
        *(uint2*)(ahi + rb + i) = hv;
        *(uint2*)(alo + rb + i) = lv;
    }
    const uint2 z2 = {0u, 0u};
    const float4 z4 = {0.f, 0.f, 0.f, 0.f};
    for (int i = L4 + t * 4; i < S_; i += 1024) {
        *(float4*)(row + i) = z4;
        if (i < Lpad) {
            *(uint2*)(ahi + rb + i) = z2;
            *(uint2*)(alo + rb + i) = z2;
        }
    }
}

// ---------------- launch ----------------
extern "C" void kernel_launch(void* const* d_in, const int* in_sizes, int n_in,
                              void* d_out, int out_size)
{
    const float* q    = (const float*)d_in[0];
    const float* k    = (const float*)d_in[1];
    const float* v    = (const float*)d_in[2];
    const float* Wq   = (const float*)d_in[4];
    const float* bq   = (const float*)d_in[5];
    const float* Wk   = (const float*)d_in[6];
    const float* bk   = (const float*)d_in[7];
    const float* Wv   = (const float*)d_in[8];
    const float* bv   = (const float*)d_in[9];
    const float* Wo   = (const float*)d_in[10];
    const float* bo   = (const float*)d_in[11];

#define SYM(p, s) cudaGetSymbolAddress((void**)&p, s)
    __nv_bfloat16 *qh, *ql, *kh, *kl, *vh, *vl;
    __nv_bfloat16 *qph, *qpl, *kph, *kpl, *vpTh, *vpTl, *ctxh, *ctxl, *ath, *atl;
    __nv_bfloat16 *WTh, *WTl;
    float *vp, *attn_scr, *z_scr;
    SYM(qh, g_q_hi);  SYM(ql, g_q_lo);
    SYM(kh, g_k_hi);  SYM(kl, g_k_lo);
    SYM(vh, g_v_hi);  SYM(vl, g_v_lo);
    SYM(qph, g_qp_hi); SYM(qpl, g_qp_lo);
    SYM(kph, g_kp_hi); SYM(kpl, g_kp_lo);
    SYM(vp, g_vp);
    SYM(vpTh, g_vpT_hi); SYM(vpTl, g_vpT_lo);
    SYM(ctxh, g_ctx_hi); SYM(ctxl, g_ctx_lo);
    SYM(ath, g_attn_hi); SYM(atl, g_attn_lo);
    SYM(WTh, (g_WT_hi[0][0]));   SYM(WTl, (g_WT_lo[0][0]));
    SYM(attn_scr, g_attn_f); SYM(z_scr, g_z);

    const size_t zN = (size_t)BS_ * D_;
    const size_t aN = (size_t)B_ * S_ * S_;
    float* out = (float*)d_out;
    float *z_out, *attn_out;
    if ((size_t)out_size >= zN + aN) { z_out = out; attn_out = out + zN; }
    else if ((size_t)out_size == aN) { attn_out = out; z_out = z_scr; }
    else                             { z_out = out; attn_out = attn_scr; }

    cudaFuncSetAttribute(gemm_mma, cudaFuncAttributeMaxDynamicSharedMemorySize, SMEM_GEMM);

    // 1) split inputs
    const int n4 = BS_ * D_ / 4;
    convert_hilo<<<(n4 + 255) / 256, 256>>>(q, qh, ql, n4);
    convert_hilo<<<(n4 + 255) / 256, 256>>>(k, kh, kl, n4);
    convert_hilo<<<(n4 + 255) / 256, 256>>>(v, vh, vl, n4);

    // 2) transpose+split weights: W [K,N] -> WT [N,K]
    dim3 tb(32, 8);
    dim3 tgw(D_ / 32, D_ / 32, 1);
    transpose_hilo<<<tgw, tb>>>(Wq, WTh + 0 * D_ * D_, WTl + 0 * D_ * D_, D_, D_);
    transpose_hilo<<<tgw, tb>>>(Wk, WTh + 1 * D_ * D_, WTl + 1 * D_ * D_, D_, D_);
    transpose_hilo<<<tgw, tb>>>(Wv, WTh + 2 * D_ * D_, WTl + 2 * D_ * D_, D_, D_);
    transpose_hilo<<<tgw, tb>>>(Wo, WTh + 3 * D_ * D_, WTl + 3 * D_ * D_, D_, D_);

    // 3) projections
    dim3 gproj(D_ / TILE_N, BS_ / TILE_M, 1);
    gemm_mma<<<gproj, 512, SMEM_GEMM>>>(qh, ql, WTh + 0 * D_ * D_, WTl + 0 * D_ * D_,
        D_, D_, 0, 0, 0, 1.f, bq, 0, nullptr, qph, qpl);
    gemm_mma<<<gproj, 512, SMEM_GEMM>>>(kh, kl, WTh + 1 * D_ * D_, WTl + 1 * D_ * D_,
        D_, D_, 0, 0, 0, 1.f, bk, 0, nullptr, kph, kpl);
    gemm_mma<<<gproj, 512, SMEM_GEMM>>>(vh, vl, WTh + 2 * D_ * D_, WTl + 2 * D_ * D_,
        D_, D_, 0, 0, 0, 1.f, bv, 0, vp, nullptr, nullptr);

    // 4) vp [B,S,D] -> vpT [B,D,S] hi/lo
    dim3 tgv(D_ / 32, S_ / 32, B_);
    transpose_hilo<<<tgv, tb>>>(vp, vpTh, vpTl, S_, D_);

    // 5) logits = qp @ kp^T / 16 + causal  (fp32 out; lower-triangle tiles only)
    dim3 glog(S_ / TILE_N, S_ / TILE_M, B_);
    gemm_mma<<<glog, 512, SMEM_GEMM>>>(qph, qpl, kph, kpl,
        S_, D_, (size_t)S_ * D_, (size_t)S_ * D_, (size_t)S_ * S_,
        1.f / 16.f, nullptr, 1, attn_out, nullptr, nullptr);

    // 6) causal softmax (+ hi/lo emit over prefix)
    softmax_kernel<<<B_ * S_, 256>>>(attn_out, ath, atl);

    // 7) ctx = attn @ vp -> hi/lo  (causal K-prefix, heavy tiles first)
    dim3 gpv(D_ / TILE_N, S_ / TILE_M, B_);
    gemm_mma<<<gpv, 512, SMEM_GEMM>>>(ath, atl, vpTh, vpTl,
        D_, S_, (size_t)S_ * S_, (size_t)D_ * S_, (size_t)S_ * D_,
        1.f, nullptr, 2, nullptr, ctxh, ctxl);

    // 8) z = ctx @ Wo + bo (fp32 out)
    gemm_mma<<<gproj, 512, SMEM_GEMM>>>(ctxh, ctxl, WTh + 3 * D_ * D_, WTl + 3 * D_ * D_,
        D_, D_, 0, 0, 0, 1.f, bo, 0, z_out, nullptr, nullptr);
}

// round 7
// speedup vs baseline: 4.3065x; 1.0335x over previous
#include <cuda_runtime.h>
#include <cuda_fp16.h>
#include <cstdint>
#include <math.h>

#define B_ 4
#define S_ 4096
#define D_ 256
#define BS_ (B_ * S_)

#define TILE_M 128
#define TILE_N 128
#define TILE_K 64

// ---------------- scratch (__device__ globals; no allocs) ----------------
__device__ __half g_q_hi[BS_ * D_], g_q_lo[BS_ * D_];
__device__ __half g_k_hi[BS_ * D_], g_k_lo[BS_ * D_];
__device__ __half g_v_hi[BS_ * D_], g_v_lo[BS_ * D_];
__device__ __half g_qp_h[BS_ * D_];                       // single fp16
__device__ __half g_kp_hi[BS_ * D_], g_kp_lo[BS_ * D_];
__device__ float  g_vp[BS_ * D_];
__device__ __half g_vpT_hi[BS_ * D_], g_vpT_lo[BS_ * D_];
__device__ __half g_ctx_hi[BS_ * D_], g_ctx_lo[BS_ * D_];
__device__ __half g_WT_hi[4][D_ * D_], g_WT_lo[4][D_ * D_];
__device__ __half g_attn_h[(size_t)B_ * S_ * S_];         // single fp16
__device__ float  g_attn_f[(size_t)B_ * S_ * S_];         // fallback
__device__ float  g_z[BS_ * D_];                          // fallback

// ---------------- helpers ----------------
__device__ __forceinline__ uint32_t smem_u32(const void* p) {
    uint32_t a;
    asm("{ .reg .u64 t; cvta.to.shared.u64 t, %1; cvt.u32.u64 %0, t; }" : "=r"(a) : "l"(p));
    return a;
}
#define SWZ128(o) ((o) ^ (((o) >> 3) & 0x70))

__device__ __forceinline__ void cpa16(uint32_t s, const void* g) {
    asm volatile("cp.async.cg.shared.global [%0], [%1], 16;" :: "r"(s), "l"(g));
}
#define CP_COMMIT() asm volatile("cp.async.commit_group;")
#define CP_WAIT1()  asm volatile("cp.async.wait_group 1;" ::: "memory")
#define CP_WAIT0()  asm volatile("cp.async.wait_group 0;" ::: "memory")

__device__ __forceinline__ void ldm_x4(uint32_t* r, uint32_t addr) {
    asm volatile("ldmatrix.sync.aligned.m8n8.x4.shared.b16 {%0,%1,%2,%3}, [%4];"
                 : "=r"(r[0]), "=r"(r[1]), "=r"(r[2]), "=r"(r[3]) : "r"(addr));
}
__device__ __forceinline__ void mma16816(float* c, const uint32_t* a, const uint32_t* b) {
    asm volatile("mma.sync.aligned.m16n8k16.row.col.f32.f16.f16.f32 "
                 "{%0,%1,%2,%3}, {%4,%5,%6,%7}, {%8,%9}, {%0,%1,%2,%3};"
                 : "+f"(c[0]), "+f"(c[1]), "+f"(c[2]), "+f"(c[3])
                 : "r"(a[0]), "r"(a[1]), "r"(a[2]), "r"(a[3]), "r"(b[0]), "r"(b[1]));
}

__device__ __forceinline__ uint32_t pack_h2(float a, float b) {
    __half2 h = __floats2half2_rn(a, b);
    return *reinterpret_cast<uint32_t*>(&h);
}
__device__ __forceinline__ void residual2(uint32_t h, float a, float b, float& ra, float& rb) {
    __half2 hh = *reinterpret_cast<__half2*>(&h);
    ra = a - __low2float(hh);
    rb = b - __high2float(hh);
}

// ----------------------------------------------------------------------------
// mma.sync fp16 GEMM:  C[z] = alpha * A[z] @ B[z]^T (+bias) (+causal)
// A: [M,K] fp16 (hi, optional lo); B: [N,K] fp16 hi/lo.
// Alo != null -> 3-term (err ~2^-24); Alo == null -> 2-term (err ~2^-12).
// 512 threads, 16 warps, CTA tile 128x128x64, double-buffered cp.async.
// cmode: 0 plain, 1 logits (skip upper-tri, causal epilogue), 2 PV (K-prefix,
//        reversed m order for load balance)
// ----------------------------------------------------------------------------
#define OFF_AH 0
#define OFF_AL 16384
#define OFF_BH 32768
#define OFF_BL 49152
#define STAGE_B 65536
#define SMEM_GEMM (2 * STAGE_B)

__device__ __forceinline__ void tile_cp(uint32_t sbase, const __half* g,
                                        size_t ldK, int tid) {
#pragma unroll
    for (int i = 0; i < 2; i++) {
        int u = tid + (i << 9);
        int r = u >> 3, c = u & 7;
        uint32_t off = (uint32_t)(r * 128 + c * 16);
        cpa16(sbase + SWZ128(off), (const char*)(g + (size_t)r * ldK) + (c << 4));
    }
}

__global__ __launch_bounds__(512, 1)
void gemm_mma(const __half* __restrict__ Ahi, const __half* __restrict__ Alo,
              const __half* __restrict__ Bhi, const __half* __restrict__ Blo,
              int N, int K,
              size_t sA, size_t sB, size_t sC,
              float alpha, const float* __restrict__ bias, int cmode,
              float* __restrict__ Cf, __half* __restrict__ Ch,
              __half* __restrict__ Chi, __half* __restrict__ Clo)
{
    int by = blockIdx.y;
    if (cmode == 2) by = gridDim.y - 1 - by;   // heavy tiles first
    const int m0 = by * TILE_M;
    const int n0 = blockIdx.x * TILE_N;
    if (cmode == 1 && n0 > m0) return;         // fully-masked logits tile

    extern __shared__ char dsm[];
    const uint32_t sb = smem_u32(dsm);
    const int tid = threadIdx.x;
    const int wid = tid >> 5;
    const int lane = tid & 31;
    const bool a3 = (Alo != nullptr);

    const int z = blockIdx.z;
    Ahi += (size_t)z * sA; if (a3) Alo += (size_t)z * sA;
    Bhi += (size_t)z * sB; Blo += (size_t)z * sB;
    if (Cf)  Cf  += (size_t)z * sC;
    if (Ch)  Ch  += (size_t)z * sC;
    if (Chi) { Chi += (size_t)z * sC; Clo += (size_t)z * sC; }

    const int mrow0 = (wid & 3) * 32;
    const int ncol0 = (wid >> 2) * 32;

    const __half* aH = Ahi + (size_t)m0 * K;
    const __half* aL = a3 ? (Alo + (size_t)m0 * K) : nullptr;
    const __half* bH = Bhi + (size_t)n0 * K;
    const __half* bL = Blo + (size_t)n0 * K;

    float acc[2][4][4];
#pragma unroll
    for (int i = 0; i < 2; i++)
#pragma unroll
        for (int j = 0; j < 4; j++)
#pragma unroll
            for (int l = 0; l < 4; l++) acc[i][j][l] = 0.f;

    int NC = K / TILE_K;
    if (cmode == 2) {
        int nc2 = (m0 >> 6) + 2;
        if (nc2 < NC) NC = nc2;
    }

    {
        const uint32_t st = sb;
        tile_cp(st + OFF_AH, aH, K, tid);
        if (a3) tile_cp(st + OFF_AL, aL, K, tid);
        tile_cp(st + OFF_BH, bH, K, tid);
        tile_cp(st + OFF_BL, bL, K, tid);
        CP_COMMIT();
    }

    const uint32_t lane15 = (uint32_t)(lane & 15);
    const uint32_t khalf = (uint32_t)((lane >> 4) << 4);

    for (int c = 0; c < NC; c++) {
        if (c + 1 < NC) {
            const uint32_t st = sb + ((c + 1) & 1) * STAGE_B;
            const size_t ko = (size_t)(c + 1) * TILE_K;
            tile_cp(st + OFF_AH, aH + ko, K, tid);
            if (a3) tile_cp(st + OFF_AL, aL + ko, K, tid);
            tile_cp(st + OFF_BH, bH + ko, K, tid);
            tile_cp(st + OFF_BL, bL + ko, K, tid);
            CP_COMMIT();
            CP_WAIT1();
        } else {
            CP_WAIT0();
        }
        __syncthreads();

        const uint32_t st = sb + (c & 1) * STAGE_B;
        const uint32_t sAh = st + OFF_AH, sAl = st + OFF_AL;
        const uint32_t sBh = st + OFF_BH, sBl = st + OFF_BL;

#pragma unroll
        for (int ks = 0; ks < 4; ks++) {
            const uint32_t kb = (uint32_t)(ks * 32) + khalf;
            uint32_t ah[2][4], al[2][4], bh[4][2], bl[4][2];
#pragma unroll
            for (int mt = 0; mt < 2; mt++) {
                const uint32_t ro = (uint32_t)(mrow0 + mt * 16) + lane15;
                ldm_x4(ah[mt], sAh + SWZ128(ro * 128 + kb));
                if (a3) ldm_x4(al[mt], sAl + SWZ128(ro * 128 + kb));
            }
#pragma unroll
            for (int g = 0; g < 2; g++) {
                const uint32_t ro = (uint32_t)(ncol0 + g * 16) + lane15;
                uint32_t t4[4];
                ldm_x4(t4, sBh + SWZ128(ro * 128 + kb));
                bh[g * 2][0] = t4[0]; bh[g * 2][1] = t4[2];
                bh[g * 2 + 1][0] = t4[1]; bh[g * 2 + 1][1] = t4[3];
                ldm_x4(t4, sBl + SWZ128(ro * 128 + kb));
                bl[g * 2][0] = t4[0]; bl[g * 2][1] = t4[2];
                bl[g * 2 + 1][0] = t4[1]; bl[g * 2 + 1][1] = t4[3];
            }
#pragma unroll
            for (int mt = 0; mt < 2; mt++)
#pragma unroll
                for (int nt = 0; nt < 4; nt++) {
                    mma16816(acc[mt][nt], ah[mt], bh[nt]);
                    mma16816(acc[mt][nt], ah[mt], bl[nt]);
                    if (a3) mma16816(acc[mt][nt], al[mt], bh[nt]);
                }
        }
        __syncthreads();
    }

    // ---- epilogue: regs -> smem stage -> coalesced gmem ----
    float* stg = (float*)dsm;
    const int ELD = 132;
    const int rr = lane >> 2;
    const int cc = (lane & 3) * 2;
#pragma unroll
    for (int mt = 0; mt < 2; mt++)
#pragma unroll
        for (int nt = 0; nt < 4; nt++) {
            const int r = mrow0 + mt * 16 + rr;
            const int cn = ncol0 + nt * 8 + cc;
            stg[r * ELD + cn]           = acc[mt][nt][0];
            stg[r * ELD + cn + 1]       = acc[mt][nt][1];
            stg[(r + 8) * ELD + cn]     = acc[mt][nt][2];
            stg[(r + 8) * ELD + cn + 1] = acc[mt][nt][3];
        }
    __syncthreads();

#pragma unroll 1
    for (int it = 0; it < 8; it++) {
        const int u = tid + (it << 9);
        const int r = u >> 5;
        const int f = (u & 31) << 2;
        const float* s = stg + r * ELD + f;
        float v0 = s[0] * alpha, v1 = s[1] * alpha, v2 = s[2] * alpha, v3 = s[3] * alpha;
        const int n = n0 + f;
        const int mi = m0 + r;
        const size_t m = (size_t)mi;
        if (bias) {
            float4 bv = *(const float4*)(bias + n);
            v0 += bv.x; v1 += bv.y; v2 += bv.z; v3 += bv.w;
        }
        if (cmode == 1) {
            if (n + 0 > mi) v0 += -1e9f;
            if (n + 1 > mi) v1 += -1e9f;
            if (n + 2 > mi) v2 += -1e9f;
            if (n + 3 > mi) v3 += -1e9f;
        }
        const size_t o = m * (size_t)N + n;
        if (Cf) {
            float4 ov = {v0, v1, v2, v3};
            *(float4*)(Cf + o) = ov;
        }
        if (Ch) {
            uint2 hv = {pack_h2(v0, v1), pack_h2(v2, v3)};
            *(uint2*)(Ch + o) = hv;
        }
        if (Chi) {
            uint32_t h0 = pack_h2(v0, v1), h1 = pack_h2(v2, v3);
            float r0, r1, r2, r3;
            residual2(h0, v0, v1, r0, r1);
            residual2(h1, v2, v3, r2, r3);
            uint2 hv = {h0, h1};
            uint2 lv = {pack_h2(r0, r1), pack_h2(r2, r3)};
            *(uint2*)(Chi + o) = hv;
            *(uint2*)(Clo + o) = lv;
        }
    }
}

// ---------------- fp32 -> (hi, lo) fp16 ----------------
__global__ __launch_bounds__(256)
void convert_hilo(const float* __restrict__ in, __half* __restrict__ hi,
                  __half* __restrict__ lo, int n4)
{
    int i = blockIdx.x * blockDim.x + threadIdx.x;
    if (i >= n4) return;
    float4 v = ((const float4*)in)[i];
    uint32_t h0 = pack_h2(v.x, v.y), h1 = pack_h2(v.z, v.w);
    float r0, r1, r2, r3;
    residual2(h0, v.x, v.y, r0, r1);
    residual2(h1, v.z, v.w, r2, r3);
    uint2 hv = {h0, h1};
    uint2 lv = {pack_h2(r0, r1), pack_h2(r2, r3)};
    ((uint2*)hi)[i] = hv;
    ((uint2*)lo)[i] = lv;
}

// ---------------- transpose + split: [Z,R,C] f32 -> [Z,C,R] fp16 hi/lo ----------------
__global__ __launch_bounds__(256)
void transpose_hilo(const float* __restrict__ in, __half* __restrict__ ohi,
                    __half* __restrict__ olo, int R, int C)
{
    __shared__ float t[32][33];
    const int z = blockIdx.z;
    in  += (size_t)z * R * C;
    ohi += (size_t)z * R * C;
    olo += (size_t)z * R * C;
    const int r0 = blockIdx.y * 32, c0 = blockIdx.x * 32;
    const int tx = threadIdx.x, ty = threadIdx.y;
#pragma unroll
    for (int j = 0; j < 32; j += 8)
        t[ty + j][tx] = in[(size_t)(r0 + ty + j) * C + c0 + tx];
    __syncthreads();
#pragma unroll
    for (int j = 0; j < 32; j += 8) {
        float v = t[tx][ty + j];
        __half h = __float2half_rn(v);
        __half l = __float2half_rn(v - __half2float(h));
        size_t o = (size_t)(c0 + ty + j) * R + r0 + tx;
        ohi[o] = h; olo[o] = l;
    }
}

// ---------------- causal softmax: prefix m+1 only; emits fp32 + fp16 single ----------------
__global__ __launch_bounds__(256)
void softmax_kernel(float* __restrict__ attn, __half* __restrict__ ah)
{
    __shared__ float buf[S_];
    __shared__ float red[8];
    __shared__ float s_max, s_sum;

    const size_t rb = (size_t)blockIdx.x * S_;
    float* row = attn + rb;
    const int t = threadIdx.x;
    const int m = blockIdx.x & (S_ - 1);
    const int L = m + 1;
    const int L4 = (L + 3) & ~3;
    const int Lpad = ((m >> 7) + 1) << 7;
    const float NINF = __int_as_float(0xff800000);

    float mx = -1e30f;
    for (int i = t * 4; i < L4; i += 1024) {
        float4 v = *(const float4*)(row + i);
        if (i + 0 >= L) v.x = NINF;
        if (i + 1 >= L) v.y = NINF;
        if (i + 2 >= L) v.z = NINF;
        if (i + 3 >= L) v.w = NINF;
        *(float4*)(buf + i) = v;
        mx = fmaxf(mx, fmaxf(fmaxf(v.x, v.y), fmaxf(v.z, v.w)));
    }
#pragma unroll
    for (int o = 16; o; o >>= 1) mx = fmaxf(mx, __shfl_xor_sync(0xffffffffu, mx, o));
    if ((t & 31) == 0) red[t >> 5] = mx;
    __syncthreads();
    if (t == 0) {
        float v = red[0];
#pragma unroll
        for (int i = 1; i < 8; i++) v = fmaxf(v, red[i]);
        s_max = v;
    }
    __syncthreads();
    const float mxv = s_max;

    float sum = 0.f;
    for (int i = t * 4; i < L4; i += 1024) {
        float4 v = *(const float4*)(buf + i);
        v.x = __expf(v.x - mxv); v.y = __expf(v.y - mxv);
        v.z = __expf(v.z - mxv); v.w = __expf(v.w - mxv);
        *(float4*)(buf + i) = v;
        sum += v.x + v.y + v.z + v.w;
    }
#pragma unroll
    for (int o = 16; o; o >>= 1) sum += __shfl_xor_sync(0xffffffffu, sum, o);
    if ((t & 31) == 0) red[t >> 5] = sum;
    __syncthreads();
    if (t == 0) {
        float v = red[0];
#pragma unroll
        for (int i = 1; i < 8; i++) v += red[i];
        s_sum = v;
    }
    __syncthreads();
    const float inv = 1.f / s_sum;

    for (int i = t * 4; i < L4; i += 1024) {
        float4 v = *(const float4*)(buf + i);
        v.x *= inv; v.y *= inv; v.z *= inv; v.w *= inv;
        *(float4*)(row + i) = v;
        uint2 hv = {pack_h2(v.x, v.y), pack_h2(v.z, v.w)};
        *(uint2*)(ah + rb + i) = hv;
    }
    const uint2 z2 = {0u, 0u};
    const float4 z4 = {0.f, 0.f, 0.f, 0.f};
    for (int i = L4 + t * 4; i < S_; i += 1024) {
        *(float4*)(row + i) = z4;
        if (i < Lpad) *(uint2*)(ah + rb + i) = z2;
    }
}

// ---------------- launch ----------------
extern "C" void kernel_launch(void* const* d_in, const int* in_sizes, int n_in,
                              void* d_out, int out_size)
{
    const float* q    = (const float*)d_in[0];
    const float* k    = (const float*)d_in[1];
    const float* v    = (const float*)d_in[2];
    const float* Wq   = (const float*)d_in[4];
    const float* bq   = (const float*)d_in[5];
    const float* Wk   = (const float*)d_in[6];
    const float* bk   = (const float*)d_in[7];
    const float* Wv   = (const float*)d_in[8];
    const float* bv   = (const float*)d_in[9];
    const float* Wo   = (const float*)d_in[10];
    const float* bo   = (const float*)d_in[11];

#define SYM(p, s) cudaGetSymbolAddress((void**)&p, s)
    __half *qh, *ql, *kh, *kl, *vh, *vl;
    __half *qph, *kph, *kpl, *vpTh, *vpTl, *ctxh, *ctxl, *ath;
    __half *WTh, *WTl;
    float *vp, *attn_scr, *z_scr;
    SYM(qh, g_q_hi);  SYM(ql, g_q_lo);
    SYM(kh, g_k_hi);  SYM(kl, g_k_lo);
    SYM(vh, g_v_hi);  SYM(vl, g_v_lo);
    SYM(qph, g_qp_h);
    SYM(kph, g_kp_hi); SYM(kpl, g_kp_lo);
    SYM(vp, g_vp);
    SYM(vpTh, g_vpT_hi); SYM(vpTl, g_vpT_lo);
    SYM(ctxh, g_ctx_hi); SYM(ctxl, g_ctx_lo);
    SYM(ath, g_attn_h);
    SYM(WTh, (g_WT_hi[0][0]));   SYM(WTl, (g_WT_lo[0][0]));
    SYM(attn_scr, g_attn_f); SYM(z_scr, g_z);

    const size_t zN = (size_t)BS_ * D_;
    const size_t aN = (size_t)B_ * S_ * S_;
    float* out = (float*)d_out;
    float *z_out, *attn_out;
    if ((size_t)out_size >= zN + aN) { z_out = out; attn_out = out + zN; }
    else if ((size_t)out_size == aN) { attn_out = out; z_out = z_scr; }
    else                             { z_out = out; attn_out = attn_scr; }

    cudaFuncSetAttribute(gemm_mma, cudaFuncAttributeMaxDynamicSharedMemorySize, SMEM_GEMM);

    // 1) split inputs (fp16 hi/lo)
    const int n4 = BS_ * D_ / 4;
    convert_hilo<<<(n4 + 255) / 256, 256>>>(q, qh, ql, n4);
    convert_hilo<<<(n4 + 255) / 256, 256>>>(k, kh, kl, n4);
    convert_hilo<<<(n4 + 255) / 256, 256>>>(v, vh, vl, n4);

    // 2) transpose+split weights: W [K,N] -> WT [N,K]
    dim3 tb(32, 8);
    dim3 tgw(D_ / 32, D_ / 32, 1);
    transpose_hilo<<<tgw, tb>>>(Wq, WTh + 0 * D_ * D_, WTl + 0 * D_ * D_, D_, D_);
    transpose_hilo<<<tgw, tb>>>(Wk, WTh + 1 * D_ * D_, WTl + 1 * D_ * D_, D_, D_);
    transpose_hilo<<<tgw, tb>>>(Wv, WTh + 2 * D_ * D_, WTl + 2 * D_ * D_, D_, D_);
    transpose_hilo<<<tgw, tb>>>(Wo, WTh + 3 * D_ * D_, WTl + 3 * D_ * D_, D_, D_);

    // 3) projections (3-term): qp -> single fp16; kp -> hi/lo; vp -> fp32
    dim3 gproj(D_ / TILE_N, BS_ / TILE_M, 1);
    gemm_mma<<<gproj, 512, SMEM_GEMM>>>(qh, ql, WTh + 0 * D_ * D_, WTl + 0 * D_ * D_,
        D_, D_, 0, 0, 0, 1.f, bq, 0, nullptr, qph, nullptr, nullptr);
    gemm_mma<<<gproj, 512, SMEM_GEMM>>>(kh, kl, WTh + 1 * D_ * D_, WTl + 1 * D_ * D_,
        D_, D_, 0, 0, 0, 1.f, bk, 0, nullptr, nullptr, kph, kpl);
    gemm_mma<<<gproj, 512, SMEM_GEMM>>>(vh, vl, WTh + 2 * D_ * D_, WTl + 2 * D_ * D_,
        D_, D_, 0, 0, 0, 1.f, bv, 0, vp, nullptr, nullptr, nullptr);

    // 4) vp [B,S,D] -> vpT [B,D,S] hi/lo
    dim3 tgv(D_ / 32, S_ / 32, B_);
    transpose_hilo<<<tgv, tb>>>(vp, vpTh, vpTl, S_, D_);

    // 5) logits = qp @ kp^T / 16 + causal (2-term; fp32 out, lower-tri tiles)
    dim3 glog(S_ / TILE_N, S_ / TILE_M, B_);
    gemm_mma<<<glog, 512, SMEM_GEMM>>>(qph, nullptr, kph, kpl,
        S_, D_, (size_t)S_ * D_, (size_t)S_ * D_, (size_t)S_ * S_,
        1.f / 16.f, nullptr, 1, attn_out, nullptr, nullptr, nullptr);

    // 6) causal softmax (+ single fp16 emit over prefix)
    softmax_kernel<<<B_ * S_, 256>>>(attn_out, ath);

    // 7) ctx = attn @ vp (2-term; causal K-prefix) -> hi/lo
    dim3 gpv(D_ / TILE_N, S_ / TILE_M, B_);
    gemm_mma<<<gpv, 512, SMEM_GEMM>>>(ath, nullptr, vpTh, vpTl,
        D_, S_, (size_t)S_ * S_, (size_t)D_ * S_, (size_t)S_ * D_,
        1.f, nullptr, 2, nullptr, nullptr, ctxh, ctxl);

    // 8) z = ctx @ Wo + bo (3-term; fp32 out)
    gemm_mma<<<gproj, 512, SMEM_GEMM>>>(ctxh, ctxl, WTh + 3 * D_ * D_, WTl + 3 * D_ * D_,
        D_, D_, 0, 0, 0, 1.f, bo, 0, z_out, nullptr, nullptr, nullptr);
}